// round 5
// baseline (speedup 1.0000x reference)
#include <cuda_runtime.h>
#include <cuda_bf16.h>
#include <math_constants.h>

#define HW 13
#define NTOK 169
#define NP 176           // padded token stride
#define NP2 352          // duplicated-pair stride (2*NP)
#define BATCH 256

typedef unsigned long long ull;

// ---- scratch (zero-initialized device globals; pads never written => stay 0) ----
__device__ __align__(16) float g_xp [BATCH * 512 * NP];   // padded x
__device__ __align__(16) float g_f8p[BATCH * 256 * NP];   // padded f8
__device__ __align__(16) float g_pool[BATCH * 128 * NP];  // padded pooled f5
__device__ __align__(16) float g_G  [BATCH * 64 * NP];    // G projection
__device__ __align__(16) float g_Fd [BATCH * 64 * NP2];   // F projection, duplicated pairs
__device__ __align__(16) float g_S  [BATCH * NP * NP];    // S (rows+cols padded)
// duplicated weights: Wd[k][2m] = Wd[k][2m+1] = W[m][k]
__device__ __align__(16) float g_fwd[512 * 128];
__device__ __align__(16) float g_gwd[512 * 128];
__device__ __align__(16) float g_hwd[256 * NP2];
__device__ __align__(16) float g_uwd[128 * NP2];
__device__ __align__(16) float g_cwd[NP  * 1024];

// ============================================================
// packed fp32x2 helpers
// ============================================================
__device__ __forceinline__ void fma2(ull& d, ull a, ull b) {
    asm("fma.rn.f32x2 %0, %1, %2, %0;" : "+l"(d) : "l"(a), "l"(b));
}
__device__ __forceinline__ ull pack2(float x, float y) {
    ull r; asm("mov.b64 %0, {%1,%2};" : "=l"(r) : "f"(x), "f"(y)); return r;
}
__device__ __forceinline__ float2 unpack2(ull v) {
    float2 f; asm("mov.b64 {%0,%1}, %2;" : "=f"(f.x), "=f"(f.y) : "l"(v)); return f;
}
__device__ __forceinline__ void cpa16(void* dst, const float* src) {
    unsigned d = (unsigned)__cvta_generic_to_shared(dst);
    asm volatile("cp.async.cg.shared.global [%0], [%1], 16;" :: "r"(d), "l"(src));
}
#define CP_COMMIT()  asm volatile("cp.async.commit_group;")
#define CP_WAIT1()   asm volatile("cp.async.wait_group 1;")
#define CP_WAIT0()   asm volatile("cp.async.wait_group 0;")

// ============================================================
// double-buffered tile, BK = 16
// ============================================================
struct __align__(16) Buf {
    ull   Ws2[16][66];    // [k][m] duplicated pairs (66 pad: 528B row, 16B-aligned)
    float Xs [16][192];   // [k][n]
};

// Wd: duplicated-layout weights, ldw floats per k-row, pre-offset by 2*m0.
// X : padded operand, NP floats per k-row. All rows valid for k0..k0+15.
__device__ __forceinline__ void fill_tile(Buf& b, const float* __restrict__ Wd, int ldw,
                                          const float* __restrict__ X, int k0, int tid)
{
#pragma unroll
    for (int i = 0; i < 2; i++) {               // 512 x 16B ops (16 rows x 512B)
        int idx = tid + i * 256;
        int kk = idx >> 5, q = idx & 31;
        cpa16(&b.Ws2[kk][q * 2], Wd + (size_t)(k0 + kk) * ldw + q * 4);
    }
#pragma unroll
    for (int i = 0; i < 3; i++) {               // 704 x 16B ops (16 rows x 44)
        int idx = tid + i * 256;
        if (idx < 704) {
            int kk = idx / 44, q = idx - kk * 44;
            cpa16(&b.Xs[kk][q * 4], X + (size_t)(k0 + kk) * NP + q * 4);
        }
    }
}

__device__ __forceinline__ void mma_tile(ull (&acc)[4][6], const Buf& b, int tx, int ty) {
#pragma unroll 4
    for (int kk = 0; kk < 16; kk++) {
        ull x[6];
#pragma unroll
        for (int jp = 0; jp < 6; jp++)
            x[jp] = *(const ull*)&b.Xs[kk][2 * tx + 32 * jp];
        ulonglong2 w01 = *(const ulonglong2*)&b.Ws2[kk][ty * 4];
        ulonglong2 w23 = *(const ulonglong2*)&b.Ws2[kk][ty * 4 + 2];
        ull w[4] = { w01.x, w01.y, w23.x, w23.y };
#pragma unroll
        for (int r = 0; r < 4; r++)
#pragma unroll
            for (int jp = 0; jp < 6; jp++)
                fma2(acc[r][jp], w[r], x[jp]);
    }
}

__device__ __forceinline__ void run_gemm(Buf* bufs, ull (&acc)[4][6],
                                         const float* __restrict__ Wd, int ldw,
                                         const float* __restrict__ X, int K,
                                         int tid, int tx, int ty)
{
    int nt = K >> 4;
    fill_tile(bufs[0], Wd, ldw, X, 0, tid);
    CP_COMMIT();
    for (int t = 0; t < nt; t++) {
        if (t + 1 < nt) {
            fill_tile(bufs[(t + 1) & 1], Wd, ldw, X, (t + 1) << 4, tid);
            CP_COMMIT();
            CP_WAIT1();
        } else {
            CP_WAIT0();
        }
        __syncthreads();
        mma_tile(acc, bufs[t & 1], tx, ty);
        __syncthreads();
    }
}

// ============================================================
// repack kernels
// ============================================================
#define X4   (BATCH * 512 * 44)
#define F84  (BATCH * 256 * 44)

__global__ __launch_bounds__(256) void repack_xf8(const float* __restrict__ x,
                                                  const float* __restrict__ f8) {
    int idx = blockIdx.x * 256 + threadIdx.x;
    const float* src; float4* dst; int q;
    if (idx < X4) {
        int row = idx / 44; q = idx - row * 44;
        src = x + (size_t)row * NTOK;
        dst = (float4*)(g_xp + (size_t)row * NP);
    } else if (idx < X4 + F84) {
        idx -= X4;
        int row = idx / 44; q = idx - row * 44;
        src = f8 + (size_t)row * NTOK;
        dst = (float4*)(g_f8p + (size_t)row * NP);
    } else return;
    int c = 4 * q;
    float4 v;
    v.x = (c     < NTOK) ? __ldg(src + c)     : 0.f;
    v.y = (c + 1 < NTOK) ? __ldg(src + c + 1) : 0.f;
    v.z = (c + 2 < NTOK) ? __ldg(src + c + 2) : 0.f;
    v.w = (c + 3 < NTOK) ? __ldg(src + c + 3) : 0.f;
    dst[q] = v;
}

#define NFW (512 * 64)
#define NHW (256 * NTOK)
#define NUW (128 * NTOK)
#define NCW (NTOK * 512)

__global__ __launch_bounds__(256) void repack_w(
    const float* __restrict__ f_w, const float* __restrict__ g_w,
    const float* __restrict__ h_w, const float* __restrict__ u_w,
    const float* __restrict__ c_w)
{
    int idx = blockIdx.x * 256 + threadIdx.x;
    float w; ull* dst;
    if (idx < NFW) {
        int k = idx >> 6, m = idx & 63;
        w = f_w[(size_t)m * 512 + k]; dst = (ull*)g_fwd + (size_t)k * 64 + m;
    } else if ((idx -= NFW) < NFW) {
        int k = idx >> 6, m = idx & 63;
        w = g_w[(size_t)m * 512 + k]; dst = (ull*)g_gwd + (size_t)k * 64 + m;
    } else if ((idx -= NFW) < NHW) {
        int k = idx / NTOK, m = idx - k * NTOK;
        w = h_w[(size_t)m * 256 + k]; dst = (ull*)g_hwd + (size_t)k * NP + m;
    } else if ((idx -= NHW) < NUW) {
        int k = idx / NTOK, m = idx - k * NTOK;
        w = u_w[(size_t)m * 128 + k]; dst = (ull*)g_uwd + (size_t)k * NP + m;
    } else if ((idx -= NUW) < NCW) {
        int k = idx >> 9, m = idx & 511;
        w = c_w[(size_t)m * NTOK + k]; dst = (ull*)g_cwd + (size_t)k * 512 + m;
    } else return;
    *dst = pack2(w, w);
}

// ============================================================
// antialiased bilinear 26 -> 13 (jax antialias=True)
// ============================================================
__constant__ int   c_tap0[HW] = { 0, 1, 3, 5, 7, 9,11,13,15,17,19,21,23};
__constant__ float c_wt[HW][4] = {
    {3.f/7.f, 3.f/7.f, 1.f/7.f, 0.f},
    {0.125f, 0.375f, 0.375f, 0.125f}, {0.125f, 0.375f, 0.375f, 0.125f},
    {0.125f, 0.375f, 0.375f, 0.125f}, {0.125f, 0.375f, 0.375f, 0.125f},
    {0.125f, 0.375f, 0.375f, 0.125f}, {0.125f, 0.375f, 0.375f, 0.125f},
    {0.125f, 0.375f, 0.375f, 0.125f}, {0.125f, 0.375f, 0.375f, 0.125f},
    {0.125f, 0.375f, 0.375f, 0.125f}, {0.125f, 0.375f, 0.375f, 0.125f},
    {0.125f, 0.375f, 0.375f, 0.125f},
    {1.f/7.f, 3.f/7.f, 3.f/7.f, 0.f}
};

__global__ __launch_bounds__(256) void pool_kernel(const float* __restrict__ f5) {
    int idx = blockIdx.x * blockDim.x + threadIdx.x;
    const int total = BATCH * 128 * NTOK;
    if (idx >= total) return;
    int n  = idx % NTOK;
    int bc = idx / NTOK;
    int j = n % HW, i = n / HW;
    const float* src = f5 + (size_t)bc * 26 * 26;
    int r0 = c_tap0[i], cc0 = c_tap0[j];
    float acc = 0.f;
#pragma unroll
    for (int ri = 0; ri < 4; ri++) {
        float wr = c_wt[i][ri];
        if (wr == 0.f) continue;
        int r = r0 + ri;
        float rowv = 0.f;
#pragma unroll
        for (int ci = 0; ci < 4; ci++) {
            float wc = c_wt[j][ci];
            if (wc == 0.f) continue;
            rowv = fmaf(wc, src[r * 26 + cc0 + ci], rowv);
        }
        acc = fmaf(wr, rowv, acc);
    }
    g_pool[(size_t)bc * NP + n] = acc;
}

// ============================================================
// F / G projections: grid (2, BATCH); F written duplicated
// ============================================================
__global__ __launch_bounds__(256, 2) void fg_kernel(
    const float* __restrict__ f_b, const float* __restrict__ g_b)
{
    __shared__ Buf bufs[2];
    int b   = blockIdx.y;
    int tid = threadIdx.x;
    int tx  = tid & 15, ty = tid >> 4;
    bool isG = blockIdx.x != 0;

    const float* Wd   = isG ? g_gwd : g_fwd;
    const float* bias = isG ? g_b   : f_b;
    const float* In   = g_xp + (size_t)b * 512 * NP;

    ull acc[4][6] = {};
    run_gemm(bufs, acc, Wd, 128, In, 512, tid, tx, ty);

#pragma unroll
    for (int r = 0; r < 4; r++) {
        int m = ty * 4 + r;
        float bv = bias[m];
        if (isG) {
            float* orow = g_G + (size_t)b * 64 * NP + (size_t)m * NP;
#pragma unroll
            for (int jp = 0; jp < 6; jp++) {
                int col = 2 * tx + 32 * jp;
                float2 v = unpack2(acc[r][jp]);
                v.x += bv; v.y += bv;
                if (col + 1 < NTOK)      *(float2*)&orow[col] = v;
                else if (col < NTOK)     orow[col] = v.x;
            }
        } else {
            ull* orow = (ull*)(g_Fd + (size_t)b * 64 * NP2 + (size_t)m * NP2);
#pragma unroll
            for (int jp = 0; jp < 6; jp++) {
                int col = 2 * tx + 32 * jp;
                float2 v = unpack2(acc[r][jp]);
                if (col     < NTOK) orow[col]     = pack2(v.x + bv, v.x + bv);
                if (col + 1 < NTOK) orow[col + 1] = pack2(v.y + bv, v.y + bv);
            }
        }
    }
}

// ============================================================
// S = softmax(F^T G) + h_w@f8 + u_w@pool + (h_b+u_b)   grid (3, BATCH)
// ============================================================
__global__ __launch_bounds__(256, 2) void s_kernel(
    const float* __restrict__ h_b, const float* __restrict__ u_b)
{
    __shared__ Buf bufs[2];
    int b   = blockIdx.y;
    int n0  = blockIdx.x * 64;
    int tid = threadIdx.x;
    int tx  = tid & 15, ty = tid >> 4;

    ull acc[4][6] = {};

    // energy = F^T G (K = 64); F duplicated layout acts as Wd
    run_gemm(bufs, acc, g_Fd + (size_t)b * 64 * NP2 + 2 * n0, NP2,
             g_G + (size_t)b * 64 * NP, 64, tid, tx, ty);

    // softmax in place over cols (16 lanes per row)
#pragma unroll
    for (int r = 0; r < 4; r++) {
        float v[12];
#pragma unroll
        for (int jp = 0; jp < 6; jp++) {
            float2 f = unpack2(acc[r][jp]);
            v[2 * jp] = f.x; v[2 * jp + 1] = f.y;
        }
        float mx = -CUDART_INF_F;
#pragma unroll
        for (int j = 0; j < 12; j++) {
            int col = 2 * tx + 32 * (j >> 1) + (j & 1);
            if (col < NTOK) mx = fmaxf(mx, v[j]);
        }
#pragma unroll
        for (int off = 8; off > 0; off >>= 1)
            mx = fmaxf(mx, __shfl_xor_sync(0xffffffffu, mx, off, 16));
        float sum = 0.f;
#pragma unroll
        for (int j = 0; j < 12; j++) {
            int col = 2 * tx + 32 * (j >> 1) + (j & 1);
            float e = (col < NTOK) ? __expf(v[j] - mx) : 0.f;
            v[j] = e; sum += e;
        }
#pragma unroll
        for (int off = 8; off > 0; off >>= 1)
            sum += __shfl_xor_sync(0xffffffffu, sum, off, 16);
        float inv = 1.f / sum;
#pragma unroll
        for (int jp = 0; jp < 6; jp++)
            acc[r][jp] = pack2(v[2 * jp] * inv, v[2 * jp + 1] * inv);
    }

    // += h_w @ f8 (K=256), += u_w @ pool (K=128)
    run_gemm(bufs, acc, g_hwd + 2 * n0, NP2, g_f8p + (size_t)b * 256 * NP, 256, tid, tx, ty);
    run_gemm(bufs, acc, g_uwd + 2 * n0, NP2, g_pool + (size_t)b * 128 * NP, 128, tid, tx, ty);

    float* Sb = g_S + (size_t)b * NP * NP;
#pragma unroll
    for (int r = 0; r < 4; r++) {
        int n = n0 + ty * 4 + r;
        if (n >= NTOK) continue;
        float bv = h_b[n] + u_b[n];
        float* srow = Sb + (size_t)n * NP;
#pragma unroll
        for (int jp = 0; jp < 6; jp++) {
            int col = 2 * tx + 32 * jp;
            float2 v = unpack2(acc[r][jp]);
            v.x += bv; v.y += bv;
            if (col + 1 < NTOK)  *(float2*)&srow[col] = v;
            else if (col < NTOK) srow[col] = v.x;
        }
    }
}

// ============================================================
// out = gamma * (c_w @ S + c_b) + x     grid (8, BATCH), K = 176 (padded)
// ============================================================
__global__ __launch_bounds__(256, 2) void out_kernel(
    const float* __restrict__ c_b,
    const float* __restrict__ x, const float* __restrict__ gamma_p,
    float* __restrict__ Out)
{
    __shared__ Buf bufs[2];
    int b   = blockIdx.y;
    int m0  = blockIdx.x * 64;
    int tid = threadIdx.x;
    int tx  = tid & 15, ty = tid >> 4;

    ull acc[4][6] = {};
    run_gemm(bufs, acc, g_cwd + 2 * m0, 1024, g_S + (size_t)b * NP * NP, NP, tid, tx, ty);

    float gma = *gamma_p;
    const float* xb = x + (size_t)b * 512 * NTOK;
    float* ob = Out + (size_t)b * 512 * NTOK;
#pragma unroll
    for (int r = 0; r < 4; r++) {
        int m = m0 + ty * 4 + r;
        float bv = c_b[m];
        const float* xrow = xb + (size_t)m * NTOK;
        float* orow = ob + (size_t)m * NTOK;
#pragma unroll
        for (int jp = 0; jp < 6; jp++) {
            int col = 2 * tx + 32 * jp;
            float2 v = unpack2(acc[r][jp]);
            if (col     < NTOK) orow[col]     = fmaf(gma, v.x + bv, xrow[col]);
            if (col + 1 < NTOK) orow[col + 1] = fmaf(gma, v.y + bv, xrow[col + 1]);
        }
    }
}

// ============================================================
extern "C" void kernel_launch(void* const* d_in, const int* in_sizes, int n_in,
                              void* d_out, int out_size)
{
    const float* x    = (const float*)d_in[0];
    const float* f5   = (const float*)d_in[1];
    const float* f8   = (const float*)d_in[2];
    const float* f_w  = (const float*)d_in[3];
    const float* f_b  = (const float*)d_in[4];
    const float* g_w  = (const float*)d_in[5];
    const float* g_b  = (const float*)d_in[6];
    const float* h_w  = (const float*)d_in[7];
    const float* h_b  = (const float*)d_in[8];
    const float* u_w  = (const float*)d_in[9];
    const float* u_b  = (const float*)d_in[10];
    const float* c_w  = (const float*)d_in[11];
    const float* c_b  = (const float*)d_in[12];
    const float* gma  = (const float*)d_in[13];

    float* out = (float*)d_out;

    repack_xf8<<<(X4 + F84 + 255) / 256, 256>>>(x, f8);
    repack_w<<<(2 * NFW + NHW + NUW + NCW + 255) / 256, 256>>>(f_w, g_w, h_w, u_w, c_w);
    {
        int total = BATCH * 128 * NTOK;
        pool_kernel<<<(total + 255) / 256, 256>>>(f5);
    }
    fg_kernel<<<dim3(2, BATCH), 256>>>(f_b, g_b);
    s_kernel<<<dim3(3, BATCH), 256>>>(h_b, u_b);
    out_kernel<<<dim3(8, BATCH), 256>>>(c_b, x, gma, out);
}

// round 6
// speedup vs baseline: 1.0130x; 1.0130x over previous
#include <cuda_runtime.h>
#include <cuda_bf16.h>
#include <math_constants.h>

#define HW 13
#define NTOK 169
#define NP 176           // padded token stride
#define NP2 352          // duplicated-pair stride (2*NP)
#define BATCH 256

typedef unsigned long long ull;

// ---- scratch (zero-initialized device globals; pads never written => stay 0) ----
__device__ __align__(16) float g_xp [BATCH * 512 * NP];   // padded x
__device__ __align__(16) float g_f8p[BATCH * 256 * NP];   // padded f8
__device__ __align__(16) float g_pool[BATCH * 128 * NP];  // padded pooled f5
__device__ __align__(16) float g_G  [BATCH * 64 * NP];    // G projection
__device__ __align__(16) float g_Fd [BATCH * 64 * NP2];   // F projection, duplicated pairs
__device__ __align__(16) float g_S  [BATCH * NP * NP];    // S (rows+cols padded)
// duplicated weights: Wd[k][2m] = Wd[k][2m+1] = W[m][k]
__device__ __align__(16) float g_fwd[512 * 128];
__device__ __align__(16) float g_gwd[512 * 128];
__device__ __align__(16) float g_hwd[256 * NP2];
__device__ __align__(16) float g_uwd[128 * NP2];
__device__ __align__(16) float g_cwd[NP  * 1024];

// ============================================================
// packed fp32x2 helpers
// ============================================================
__device__ __forceinline__ void fma2(ull& d, ull a, ull b) {
    asm("fma.rn.f32x2 %0, %1, %2, %0;" : "+l"(d) : "l"(a), "l"(b));
}
__device__ __forceinline__ ull pack2(float x, float y) {
    ull r; asm("mov.b64 %0, {%1,%2};" : "=l"(r) : "f"(x), "f"(y)); return r;
}
__device__ __forceinline__ float2 unpack2(ull v) {
    float2 f; asm("mov.b64 {%0,%1}, %2;" : "=f"(f.x), "=f"(f.y) : "l"(v)); return f;
}
__device__ __forceinline__ void cpa16(void* dst, const float* src) {
    unsigned d = (unsigned)__cvta_generic_to_shared(dst);
    asm volatile("cp.async.cg.shared.global [%0], [%1], 16;" :: "r"(d), "l"(src));
}
#define CP_COMMIT()  asm volatile("cp.async.commit_group;")
#define CP_WAIT0()   asm volatile("cp.async.wait_group 0;")

// ============================================================
// double-buffered tile, BK = 16
// ============================================================
struct __align__(16) Buf {
    ull   Ws2[16][66];    // [k][m] duplicated pairs
    float Xs [16][192];   // [k][n]
};

__device__ __forceinline__ void fill_tile(Buf& b, const float* __restrict__ Wd, int ldw,
                                          const float* __restrict__ X, int k0, int tid)
{
#pragma unroll
    for (int i = 0; i < 2; i++) {               // 512 x 16B (16 rows x 512B of W pairs)
        int idx = tid + i * 256;
        int kk = idx >> 5, q = idx & 31;
        cpa16(&b.Ws2[kk][q * 2], Wd + (size_t)(k0 + kk) * ldw + q * 4);
    }
#pragma unroll
    for (int i = 0; i < 3; i++) {               // 704 x 16B (16 rows x 176 floats)
        int idx = tid + i * 256;
        if (idx < 704) {
            int kk = idx / 44, q = idx - kk * 44;
            cpa16(&b.Xs[kk][q * 4], X + (size_t)(k0 + kk) * NP + q * 4);
        }
    }
}

__device__ __forceinline__ void mma_tile(ull (&acc)[4][6], const Buf& b, int tx, int ty) {
#pragma unroll 4
    for (int kk = 0; kk < 16; kk++) {
        ull x[6];
#pragma unroll
        for (int jp = 0; jp < 6; jp++)
            x[jp] = *(const ull*)&b.Xs[kk][2 * tx + 32 * jp];
        ulonglong2 w01 = *(const ulonglong2*)&b.Ws2[kk][ty * 4];
        ulonglong2 w23 = *(const ulonglong2*)&b.Ws2[kk][ty * 4 + 2];
        ull w[4] = { w01.x, w01.y, w23.x, w23.y };
#pragma unroll
        for (int r = 0; r < 4; r++)
#pragma unroll
            for (int jp = 0; jp < 6; jp++)
                fma2(acc[r][jp], w[r], x[jp]);
    }
}

// single-sync double-buffer pipeline:
//   per tile: wait(fill t) -> barrier -> issue fill(t+1) -> mma(t)
// trailing barrier protects buffer reuse by a following run_gemm.
__device__ __forceinline__ void run_gemm(Buf* bufs, ull (&acc)[4][6],
                                         const float* __restrict__ Wd, int ldw,
                                         const float* __restrict__ X, int K,
                                         int tid, int tx, int ty)
{
    int nt = K >> 4;
    fill_tile(bufs[0], Wd, ldw, X, 0, tid);
    CP_COMMIT();
    for (int t = 0; t < nt; t++) {
        CP_WAIT0();            // the single in-flight group == fill of tile t
        __syncthreads();       // visibility + everyone done with buf[(t+1)&1]
        if (t + 1 < nt) {
            fill_tile(bufs[(t + 1) & 1], Wd, ldw, X, (t + 1) << 4, tid);
            CP_COMMIT();
        }
        mma_tile(acc, bufs[t & 1], tx, ty);
    }
    __syncthreads();           // protect buffers before any subsequent run_gemm
}

// ============================================================
// repack kernels
// ============================================================
#define X4   (BATCH * 512 * 44)
#define F84  (BATCH * 256 * 44)

__global__ __launch_bounds__(256) void repack_xf8(const float* __restrict__ x,
                                                  const float* __restrict__ f8) {
    int idx = blockIdx.x * 256 + threadIdx.x;
    const float* src; float4* dst; int q;
    if (idx < X4) {
        int row = idx / 44; q = idx - row * 44;
        src = x + (size_t)row * NTOK;
        dst = (float4*)(g_xp + (size_t)row * NP);
    } else if (idx < X4 + F84) {
        idx -= X4;
        int row = idx / 44; q = idx - row * 44;
        src = f8 + (size_t)row * NTOK;
        dst = (float4*)(g_f8p + (size_t)row * NP);
    } else return;
    int c = 4 * q;
    float4 v;
    v.x = (c     < NTOK) ? __ldg(src + c)     : 0.f;
    v.y = (c + 1 < NTOK) ? __ldg(src + c + 1) : 0.f;
    v.z = (c + 2 < NTOK) ? __ldg(src + c + 2) : 0.f;
    v.w = (c + 3 < NTOK) ? __ldg(src + c + 3) : 0.f;
    dst[q] = v;
}

#define NFW (512 * 64)
#define NHW (256 * NTOK)
#define NUW (128 * NTOK)
#define NCW (NTOK * 512)

__global__ __launch_bounds__(256) void repack_w(
    const float* __restrict__ f_w, const float* __restrict__ g_w,
    const float* __restrict__ h_w, const float* __restrict__ u_w,
    const float* __restrict__ c_w)
{
    int idx = blockIdx.x * 256 + threadIdx.x;
    float w; ull* dst;
    if (idx < NFW) {
        int k = idx >> 6, m = idx & 63;
        w = f_w[(size_t)m * 512 + k]; dst = (ull*)g_fwd + (size_t)k * 64 + m;
    } else if ((idx -= NFW) < NFW) {
        int k = idx >> 6, m = idx & 63;
        w = g_w[(size_t)m * 512 + k]; dst = (ull*)g_gwd + (size_t)k * 64 + m;
    } else if ((idx -= NFW) < NHW) {
        int k = idx / NTOK, m = idx - k * NTOK;
        w = h_w[(size_t)m * 256 + k]; dst = (ull*)g_hwd + (size_t)k * NP + m;
    } else if ((idx -= NHW) < NUW) {
        int k = idx / NTOK, m = idx - k * NTOK;
        w = u_w[(size_t)m * 128 + k]; dst = (ull*)g_uwd + (size_t)k * NP + m;
    } else if ((idx -= NUW) < NCW) {
        int k = idx >> 9, m = idx & 511;
        w = c_w[(size_t)m * NTOK + k]; dst = (ull*)g_cwd + (size_t)k * 512 + m;
    } else return;
    *dst = pack2(w, w);
}

// ============================================================
// antialiased bilinear 26 -> 13 (jax antialias=True)
// ============================================================
__constant__ int   c_tap0[HW] = { 0, 1, 3, 5, 7, 9,11,13,15,17,19,21,23};
__constant__ float c_wt[HW][4] = {
    {3.f/7.f, 3.f/7.f, 1.f/7.f, 0.f},
    {0.125f, 0.375f, 0.375f, 0.125f}, {0.125f, 0.375f, 0.375f, 0.125f},
    {0.125f, 0.375f, 0.375f, 0.125f}, {0.125f, 0.375f, 0.375f, 0.125f},
    {0.125f, 0.375f, 0.375f, 0.125f}, {0.125f, 0.375f, 0.375f, 0.125f},
    {0.125f, 0.375f, 0.375f, 0.125f}, {0.125f, 0.375f, 0.375f, 0.125f},
    {0.125f, 0.375f, 0.375f, 0.125f}, {0.125f, 0.375f, 0.375f, 0.125f},
    {0.125f, 0.375f, 0.375f, 0.125f},
    {1.f/7.f, 3.f/7.f, 3.f/7.f, 0.f}
};

__global__ __launch_bounds__(256) void pool_kernel(const float* __restrict__ f5) {
    int idx = blockIdx.x * blockDim.x + threadIdx.x;
    const int total = BATCH * 128 * NTOK;
    if (idx >= total) return;
    int n  = idx % NTOK;
    int bc = idx / NTOK;
    int j = n % HW, i = n / HW;
    const float* src = f5 + (size_t)bc * 26 * 26;
    int r0 = c_tap0[i], cc0 = c_tap0[j];
    float acc = 0.f;
#pragma unroll
    for (int ri = 0; ri < 4; ri++) {
        float wr = c_wt[i][ri];
        if (wr == 0.f) continue;
        int r = r0 + ri;
        float rowv = 0.f;
#pragma unroll
        for (int ci = 0; ci < 4; ci++) {
            float wc = c_wt[j][ci];
            if (wc == 0.f) continue;
            rowv = fmaf(wc, src[r * 26 + cc0 + ci], rowv);
        }
        acc = fmaf(wr, rowv, acc);
    }
    g_pool[(size_t)bc * NP + n] = acc;
}

// ============================================================
// F / G projections: grid (2, BATCH); F written duplicated
// ============================================================
__global__ __launch_bounds__(256, 2) void fg_kernel(
    const float* __restrict__ f_b, const float* __restrict__ g_b)
{
    __shared__ Buf bufs[2];
    int b   = blockIdx.y;
    int tid = threadIdx.x;
    int tx  = tid & 15, ty = tid >> 4;
    bool isG = blockIdx.x != 0;

    const float* Wd   = isG ? g_gwd : g_fwd;
    const float* bias = isG ? g_b   : f_b;
    const float* In   = g_xp + (size_t)b * 512 * NP;

    ull acc[4][6] = {};
    run_gemm(bufs, acc, Wd, 128, In, 512, tid, tx, ty);

#pragma unroll
    for (int r = 0; r < 4; r++) {
        int m = ty * 4 + r;
        float bv = bias[m];
        if (isG) {
            float* orow = g_G + (size_t)b * 64 * NP + (size_t)m * NP;
#pragma unroll
            for (int jp = 0; jp < 6; jp++) {
                int col = 2 * tx + 32 * jp;
                float2 v = unpack2(acc[r][jp]);
                v.x += bv; v.y += bv;
                if (col + 1 < NTOK)      *(float2*)&orow[col] = v;
                else if (col < NTOK)     orow[col] = v.x;
            }
        } else {
            ull* orow = (ull*)(g_Fd + (size_t)b * 64 * NP2 + (size_t)m * NP2);
#pragma unroll
            for (int jp = 0; jp < 6; jp++) {
                int col = 2 * tx + 32 * jp;
                float2 v = unpack2(acc[r][jp]);
                if (col     < NTOK) orow[col]     = pack2(v.x + bv, v.x + bv);
                if (col + 1 < NTOK) orow[col + 1] = pack2(v.y + bv, v.y + bv);
            }
        }
    }
}

// ============================================================
// S = softmax(F^T G) + h_w@f8 + u_w@pool + (h_b+u_b)   grid (3, BATCH)
// ============================================================
__global__ __launch_bounds__(256, 2) void s_kernel(
    const float* __restrict__ h_b, const float* __restrict__ u_b)
{
    __shared__ Buf bufs[2];
    int b   = blockIdx.y;
    int n0  = blockIdx.x * 64;
    int tid = threadIdx.x;
    int tx  = tid & 15, ty = tid >> 4;

    ull acc[4][6] = {};

    // energy = F^T G (K = 64); F duplicated layout acts as Wd
    run_gemm(bufs, acc, g_Fd + (size_t)b * 64 * NP2 + 2 * n0, NP2,
             g_G + (size_t)b * 64 * NP, 64, tid, tx, ty);

    // softmax in place over cols (16 lanes per row)
#pragma unroll
    for (int r = 0; r < 4; r++) {
        float v[12];
#pragma unroll
        for (int jp = 0; jp < 6; jp++) {
            float2 f = unpack2(acc[r][jp]);
            v[2 * jp] = f.x; v[2 * jp + 1] = f.y;
        }
        float mx = -CUDART_INF_F;
#pragma unroll
        for (int j = 0; j < 12; j++) {
            int col = 2 * tx + 32 * (j >> 1) + (j & 1);
            if (col < NTOK) mx = fmaxf(mx, v[j]);
        }
#pragma unroll
        for (int off = 8; off > 0; off >>= 1)
            mx = fmaxf(mx, __shfl_xor_sync(0xffffffffu, mx, off, 16));
        float sum = 0.f;
#pragma unroll
        for (int j = 0; j < 12; j++) {
            int col = 2 * tx + 32 * (j >> 1) + (j & 1);
            float e = (col < NTOK) ? __expf(v[j] - mx) : 0.f;
            v[j] = e; sum += e;
        }
#pragma unroll
        for (int off = 8; off > 0; off >>= 1)
            sum += __shfl_xor_sync(0xffffffffu, sum, off, 16);
        float inv = 1.f / sum;
#pragma unroll
        for (int jp = 0; jp < 6; jp++)
            acc[r][jp] = pack2(v[2 * jp] * inv, v[2 * jp + 1] * inv);
    }

    // += h_w @ f8 (K=256), += u_w @ pool (K=128)
    run_gemm(bufs, acc, g_hwd + 2 * n0, NP2, g_f8p + (size_t)b * 256 * NP, 256, tid, tx, ty);
    run_gemm(bufs, acc, g_uwd + 2 * n0, NP2, g_pool + (size_t)b * 128 * NP, 128, tid, tx, ty);

    float* Sb = g_S + (size_t)b * NP * NP;
#pragma unroll
    for (int r = 0; r < 4; r++) {
        int n = n0 + ty * 4 + r;
        if (n >= NTOK) continue;
        float bv = h_b[n] + u_b[n];
        float* srow = Sb + (size_t)n * NP;
#pragma unroll
        for (int jp = 0; jp < 6; jp++) {
            int col = 2 * tx + 32 * jp;
            float2 v = unpack2(acc[r][jp]);
            v.x += bv; v.y += bv;
            if (col + 1 < NTOK)  *(float2*)&srow[col] = v;
            else if (col < NTOK) srow[col] = v.x;
        }
    }
}

// ============================================================
// out = gamma * (c_w @ S + c_b) + x     grid (8, BATCH), K = 176 (padded)
// ============================================================
__global__ __launch_bounds__(256, 2) void out_kernel(
    const float* __restrict__ c_b,
    const float* __restrict__ x, const float* __restrict__ gamma_p,
    float* __restrict__ Out)
{
    __shared__ Buf bufs[2];
    int b   = blockIdx.y;
    int m0  = blockIdx.x * 64;
    int tid = threadIdx.x;
    int tx  = tid & 15, ty = tid >> 4;

    ull acc[4][6] = {};
    run_gemm(bufs, acc, g_cwd + 2 * m0, 1024, g_S + (size_t)b * NP * NP, NP, tid, tx, ty);

    float gma = *gamma_p;
    const float* xb = x + (size_t)b * 512 * NTOK;
    float* ob = Out + (size_t)b * 512 * NTOK;
#pragma unroll
    for (int r = 0; r < 4; r++) {
        int m = m0 + ty * 4 + r;
        float bv = c_b[m];
        const float* xrow = xb + (size_t)m * NTOK;
        float* orow = ob + (size_t)m * NTOK;
#pragma unroll
        for (int jp = 0; jp < 6; jp++) {
            int col = 2 * tx + 32 * jp;
            float2 v = unpack2(acc[r][jp]);
            if (col     < NTOK) orow[col]     = fmaf(gma, v.x + bv, xrow[col]);
            if (col + 1 < NTOK) orow[col + 1] = fmaf(gma, v.y + bv, xrow[col + 1]);
        }
    }
}

// ============================================================
extern "C" void kernel_launch(void* const* d_in, const int* in_sizes, int n_in,
                              void* d_out, int out_size)
{
    const float* x    = (const float*)d_in[0];
    const float* f5   = (const float*)d_in[1];
    const float* f8   = (const float*)d_in[2];
    const float* f_w  = (const float*)d_in[3];
    const float* f_b  = (const float*)d_in[4];
    const float* g_w  = (const float*)d_in[5];
    const float* g_b  = (const float*)d_in[6];
    const float* h_w  = (const float*)d_in[7];
    const float* h_b  = (const float*)d_in[8];
    const float* u_w  = (const float*)d_in[9];
    const float* u_b  = (const float*)d_in[10];
    const float* c_w  = (const float*)d_in[11];
    const float* c_b  = (const float*)d_in[12];
    const float* gma  = (const float*)d_in[13];

    float* out = (float*)d_out;

    repack_xf8<<<(X4 + F84 + 255) / 256, 256>>>(x, f8);
    repack_w<<<(2 * NFW + NHW + NUW + NCW + 255) / 256, 256>>>(f_w, g_w, h_w, u_w, c_w);
    {
        int total = BATCH * 128 * NTOK;
        pool_kernel<<<(total + 255) / 256, 256>>>(f5);
    }
    fg_kernel<<<dim3(2, BATCH), 256>>>(f_b, g_b);
    s_kernel<<<dim3(3, BATCH), 256>>>(h_b, u_b);
    out_kernel<<<dim3(8, BATCH), 256>>>(c_b, x, gma, out);
}

// round 7
// speedup vs baseline: 1.3277x; 1.3108x over previous
#include <cuda_runtime.h>
#include <cuda_bf16.h>
#include <math_constants.h>

#define HW 13
#define NTOK 169
#define BNP 192          // bf16 B-operand column stride
#define BATCH 256

typedef __nv_bfloat16 bf;

// ---- B-operand streams: [k2][BNP] bf16, rows interleaved (2k=hi, 2k+1=lo) ----
__device__ __align__(16) bf g_xhl [BATCH * 1024 * BNP];
__device__ __align__(16) bf g_f8hl[BATCH * 512 * BNP];
__device__ __align__(16) bf g_phl [BATCH * 256 * BNP];
__device__ __align__(16) bf g_Ghl [BATCH * 128 * BNP];
__device__ __align__(16) bf g_Shl [BATCH * 352 * BNP];
// ---- A-operand streams: [m][k2] bf16, values duplicated pairwise along k2 ----
__device__ __align__(16) bf g_fwh[64 * 1024],  g_fwl[64 * 1024];
__device__ __align__(16) bf g_gwh[64 * 1024],  g_gwl[64 * 1024];
__device__ __align__(16) bf g_hwh[192 * 512],  g_hwl[192 * 512];
__device__ __align__(16) bf g_uwh[192 * 256],  g_uwl[192 * 256];
__device__ __align__(16) bf g_cwh[512 * 352],  g_cwl[512 * 352];
__device__ __align__(16) bf g_Fh [BATCH * 192 * 128], g_Fl[BATCH * 192 * 128];
// ---- fp32 S (rows/cols 169, stride 176; pads stay zero) ----
__device__ __align__(16) float g_S[BATCH * 176 * 176];

// ============================================================
// low-level helpers
// ============================================================
__device__ __forceinline__ unsigned smem_u32(const void* p) {
    return (unsigned)__cvta_generic_to_shared(p);
}
__device__ __forceinline__ void cpa16(void* dst, const void* src) {
    asm volatile("cp.async.cg.shared.global [%0], [%1], 16;"
                 :: "r"(smem_u32(dst)), "l"(src));
}
#define CP_COMMIT()  asm volatile("cp.async.commit_group;")
#define CP_WAIT0()   asm volatile("cp.async.wait_group 0;")

__device__ __forceinline__ void ldsm_x4(unsigned (&r)[4], unsigned a) {
    asm volatile("ldmatrix.sync.aligned.m8n8.x4.shared.b16 {%0,%1,%2,%3}, [%4];"
        : "=r"(r[0]), "=r"(r[1]), "=r"(r[2]), "=r"(r[3]) : "r"(a));
}
__device__ __forceinline__ void ldsm_x4t(unsigned (&r)[4], unsigned a) {
    asm volatile("ldmatrix.sync.aligned.m8n8.x4.trans.shared.b16 {%0,%1,%2,%3}, [%4];"
        : "=r"(r[0]), "=r"(r[1]), "=r"(r[2]), "=r"(r[3]) : "r"(a));
}
__device__ __forceinline__ void ldsm_x2t(unsigned (&r)[2], unsigned a) {
    asm volatile("ldmatrix.sync.aligned.m8n8.x2.trans.shared.b16 {%0,%1}, [%2];"
        : "=r"(r[0]), "=r"(r[1]) : "r"(a));
}
__device__ __forceinline__ void mma16816(float (&d)[4], const unsigned (&a)[4],
                                         unsigned b0, unsigned b1) {
    asm volatile("mma.sync.aligned.m16n8k16.row.col.f32.bf16.bf16.f32 "
        "{%0,%1,%2,%3}, {%4,%5,%6,%7}, {%8,%9}, {%0,%1,%2,%3};"
        : "+f"(d[0]), "+f"(d[1]), "+f"(d[2]), "+f"(d[3])
        : "r"(a[0]), "r"(a[1]), "r"(a[2]), "r"(a[3]), "r"(b0), "r"(b1));
}
__device__ __forceinline__ void split_bf(float v, bf& hi, bf& lo) {
    hi = __float2bfloat16(v);
    lo = __float2bfloat16(v - __bfloat162float(hi));
}

// ============================================================
// smem: double-buffered A(hi), A(lo), B tiles.  K2 chunk = 32.
// A: [64][40] bf16 (pad 40 -> conflict-free ldmatrix)
// B: [32][184] bf16 (pad 184 -> conflict-free ldmatrix.trans)
// ============================================================
struct Smem {
    bf Ah[2][64][40];
    bf Al[2][64][40];
    bf Bs[2][32][184];
};

__device__ __forceinline__ void fill(Smem& s, int buf,
                                     const bf* __restrict__ Ah, const bf* __restrict__ Al,
                                     int lda2, const bf* __restrict__ B, int k20, int tid)
{
#pragma unroll
    for (int i = 0; i < 2; i++) {       // 512 x 16B : A hi/lo tiles
        int idx = tid + i * 256;
        int var = idx >> 8;
        int rr  = (idx >> 2) & 63, q = idx & 3;
        const bf* src = (var ? Al : Ah) + (size_t)rr * lda2 + k20 + q * 8;
        bf* dst = var ? &s.Al[buf][rr][q * 8] : &s.Ah[buf][rr][q * 8];
        cpa16(dst, src);
    }
#pragma unroll
    for (int i = 0; i < 3; i++) {       // 736 x 16B : B tile (32 rows x 184 bf16)
        int idx = tid + i * 256;
        if (idx < 736) {
            int rr = idx / 23, q = idx - rr * 23;
            cpa16(&s.Bs[buf][rr][q * 8], B + (size_t)(k20 + rr) * BNP + q * 8);
        }
    }
}

__device__ __forceinline__ void mma_chunk(float (&acc)[11][4], Smem& s, int buf,
                                          int lane, int wm, int wn)
{
    unsigned rsel = lane & 15;
    unsigned csel = (lane >> 4) << 3;   // 0 or 8
#pragma unroll
    for (int ks = 0; ks < 32; ks += 16) {
        unsigned ah[4], al[4];
        ldsm_x4(ah, smem_u32(&s.Ah[buf][wm * 16 + rsel][ks + csel]));
        ldsm_x4(al, smem_u32(&s.Al[buf][wm * 16 + rsel][ks + csel]));
#pragma unroll
        for (int g = 0; g < 5; g++) {
            unsigned bb[4];
            ldsm_x4t(bb, smem_u32(&s.Bs[buf][ks + rsel][wn * 88 + g * 16 + csel]));
            mma16816(acc[2 * g],     ah, bb[0], bb[1]);
            mma16816(acc[2 * g],     al, bb[0], bb[1]);
            mma16816(acc[2 * g + 1], ah, bb[2], bb[3]);
            mma16816(acc[2 * g + 1], al, bb[2], bb[3]);
        }
        unsigned bt[2];
        ldsm_x2t(bt, smem_u32(&s.Bs[buf][ks + rsel][wn * 88 + 80]));
        mma16816(acc[10], ah, bt[0], bt[1]);
        mma16816(acc[10], al, bt[0], bt[1]);
    }
}

__device__ __forceinline__ void run_gemm(Smem& s, float (&acc)[11][4],
                                         const bf* __restrict__ Ah, const bf* __restrict__ Al,
                                         int lda2, const bf* __restrict__ B, int K2,
                                         int tid, int lane, int wm, int wn)
{
    int nt = K2 >> 5;
    fill(s, 0, Ah, Al, lda2, B, 0, tid);
    CP_COMMIT();
    for (int t = 0; t < nt; t++) {
        CP_WAIT0();
        __syncthreads();
        if (t + 1 < nt) {
            fill(s, (t + 1) & 1, Ah, Al, lda2, B, (t + 1) * 32, tid);
            CP_COMMIT();
        }
        mma_chunk(acc, s, t & 1, lane, wm, wn);
    }
    __syncthreads();
}

// ============================================================
// split / repack kernels
// ============================================================
__global__ __launch_bounds__(256) void split_w_kernel(
    const float* __restrict__ f_w, const float* __restrict__ g_w,
    const float* __restrict__ h_w, const float* __restrict__ u_w,
    const float* __restrict__ c_w)
{
    int idx = blockIdx.x * 256 + threadIdx.x;
    float v; bf *dh, *dl;
    if (idx < 64 * 512) {
        int m = idx >> 9, k = idx & 511;
        v = f_w[idx]; dh = g_fwh + (size_t)m * 1024 + 2 * k; dl = g_fwl + (size_t)m * 1024 + 2 * k;
    } else if ((idx -= 64 * 512) < 64 * 512) {
        int m = idx >> 9, k = idx & 511;
        v = g_w[idx]; dh = g_gwh + (size_t)m * 1024 + 2 * k; dl = g_gwl + (size_t)m * 1024 + 2 * k;
    } else if ((idx -= 64 * 512) < 169 * 256) {
        int m = idx >> 8, k = idx & 255;
        v = h_w[idx]; dh = g_hwh + (size_t)m * 512 + 2 * k; dl = g_hwl + (size_t)m * 512 + 2 * k;
    } else if ((idx -= 169 * 256) < 169 * 128) {
        int m = idx >> 7, k = idx & 127;
        v = u_w[idx]; dh = g_uwh + (size_t)m * 256 + 2 * k; dl = g_uwl + (size_t)m * 256 + 2 * k;
    } else if ((idx -= 169 * 128) < 512 * 169) {
        int m = idx / 169, k = idx - m * 169;
        v = c_w[idx]; dh = g_cwh + (size_t)m * 352 + 2 * k; dl = g_cwl + (size_t)m * 352 + 2 * k;
    } else return;
    bf hi, lo; split_bf(v, hi, lo);
    dh[0] = hi; dh[1] = hi; dl[0] = lo; dl[1] = lo;
}

#define XE (BATCH * 512 * NTOK)
#define FE (BATCH * 256 * NTOK)
__global__ __launch_bounds__(256) void split_x_kernel(const float* __restrict__ x,
                                                      const float* __restrict__ f8)
{
    int idx = blockIdx.x * 256 + threadIdx.x;
    const float* src; bf* base;
    if (idx < XE)       { src = x;  base = g_xhl; }
    else if ((idx -= XE) < FE) { src = f8; base = g_f8hl; }
    else return;
    int row = idx / NTOK, n = idx - row * NTOK;
    bf hi, lo; split_bf(src[idx], hi, lo);
    bf* d = base + (size_t)(2 * row) * BNP + n;
    d[0] = hi; d[BNP] = lo;
}

__global__ __launch_bounds__(256) void split_s_kernel()
{
    int idx = blockIdx.x * 256 + threadIdx.x;
    if (idx >= BATCH * 176 * 176) return;
    int row = idx / 176, n = idx - row * 176;
    bf hi, lo; split_bf(g_S[idx], hi, lo);
    bf* d = g_Shl + (size_t)(2 * row) * BNP + n;
    d[0] = hi; d[BNP] = lo;
}

// ============================================================
// antialiased bilinear 26 -> 13 (jax antialias=True), writes split bf16
// ============================================================
__constant__ int   c_tap0[HW] = { 0, 1, 3, 5, 7, 9,11,13,15,17,19,21,23};
__constant__ float c_wt[HW][4] = {
    {3.f/7.f, 3.f/7.f, 1.f/7.f, 0.f},
    {0.125f, 0.375f, 0.375f, 0.125f}, {0.125f, 0.375f, 0.375f, 0.125f},
    {0.125f, 0.375f, 0.375f, 0.125f}, {0.125f, 0.375f, 0.375f, 0.125f},
    {0.125f, 0.375f, 0.375f, 0.125f}, {0.125f, 0.375f, 0.375f, 0.125f},
    {0.125f, 0.375f, 0.375f, 0.125f}, {0.125f, 0.375f, 0.375f, 0.125f},
    {0.125f, 0.375f, 0.375f, 0.125f}, {0.125f, 0.375f, 0.375f, 0.125f},
    {0.125f, 0.375f, 0.375f, 0.125f},
    {1.f/7.f, 3.f/7.f, 3.f/7.f, 0.f}
};

__global__ __launch_bounds__(256) void pool_kernel(const float* __restrict__ f5) {
    int idx = blockIdx.x * blockDim.x + threadIdx.x;
    if (idx >= BATCH * 128 * NTOK) return;
    int n  = idx % NTOK;
    int bc = idx / NTOK;
    int j = n % HW, i = n / HW;
    const float* src = f5 + (size_t)bc * 26 * 26;
    int r0 = c_tap0[i], cc0 = c_tap0[j];
    float acc = 0.f;
#pragma unroll
    for (int ri = 0; ri < 4; ri++) {
        float wr = c_wt[i][ri];
        if (wr == 0.f) continue;
        int r = r0 + ri;
        float rowv = 0.f;
#pragma unroll
        for (int ci = 0; ci < 4; ci++) {
            float wc = c_wt[j][ci];
            if (wc == 0.f) continue;
            rowv = fmaf(wc, src[r * 26 + cc0 + ci], rowv);
        }
        acc = fmaf(wr, rowv, acc);
    }
    bf hi, lo; split_bf(acc, hi, lo);
    bf* d = g_phl + (size_t)(2 * bc) * BNP + n;
    d[0] = hi; d[BNP] = lo;
}

// ============================================================
// F / G projections: grid (2, BATCH); F written as A-stream, G as B-stream
// ============================================================
__global__ __launch_bounds__(256, 2) void fg_kernel(const float* __restrict__ f_b,
                                                    const float* __restrict__ g_b)
{
    __shared__ Smem s;
    int b   = blockIdx.y;
    bool isG = blockIdx.x != 0;
    int tid = threadIdx.x, lane = tid & 31, wid = tid >> 5;
    int wm = wid & 3, wn = wid >> 2;

    float acc[11][4] = {};
    run_gemm(s, acc, isG ? g_gwh : g_fwh, isG ? g_gwl : g_fwl, 1024,
             g_xhl + (size_t)b * 1024 * BNP, 1024, tid, lane, wm, wn);

    const float* bias = isG ? g_b : f_b;
    int lr = lane >> 2, lc = (lane & 3) * 2;
#pragma unroll
    for (int half = 0; half < 2; half++) {
        int m = wm * 16 + lr + half * 8;      // output channel 0..63
        float bv = bias[m];
#pragma unroll
        for (int t = 0; t < 11; t++) {
#pragma unroll
            for (int e = 0; e < 2; e++) {
                int n = wn * 88 + t * 8 + lc + e;
                if (n >= NTOK) continue;
                float v = acc[t][half * 2 + e] + bv;
                bf hi, lo; split_bf(v, hi, lo);
                if (isG) {
                    bf* d = g_Ghl + (size_t)b * 128 * BNP + (size_t)(2 * m) * BNP + n;
                    d[0] = hi; d[BNP] = lo;
                } else {
                    size_t o = (size_t)b * 192 * 128 + (size_t)n * 128 + 2 * m;
                    g_Fh[o] = hi; g_Fh[o + 1] = hi;
                    g_Fl[o] = lo; g_Fl[o + 1] = lo;
                }
            }
        }
    }
}

// ============================================================
// S = softmax(F^T G) + h_w@f8 + u_w@pool + bias     grid (3, BATCH)
// ============================================================
__global__ __launch_bounds__(256, 2) void s_kernel(const float* __restrict__ h_b,
                                                   const float* __restrict__ u_b)
{
    __shared__ Smem s;
    __shared__ float redM[2][64], redS[2][64];
    int b   = blockIdx.y;
    int m0  = blockIdx.x * 64;
    int tid = threadIdx.x, lane = tid & 31, wid = tid >> 5;
    int wm = wid & 3, wn = wid >> 2;
    int lr = lane >> 2, lc = (lane & 3) * 2;

    float acc[11][4] = {};

    // energy = F^T G  (K2 = 128)
    run_gemm(s, acc, g_Fh + (size_t)b * 192 * 128 + (size_t)m0 * 128,
                     g_Fl + (size_t)b * 192 * 128 + (size_t)m0 * 128, 128,
             g_Ghl + (size_t)b * 128 * BNP, 128, tid, lane, wm, wn);

    // ---- softmax over cols (rows split across 2 N-warps) ----
    float pmax[2] = { -CUDART_INF_F, -CUDART_INF_F };
#pragma unroll
    for (int half = 0; half < 2; half++)
#pragma unroll
        for (int t = 0; t < 11; t++)
#pragma unroll
            for (int e = 0; e < 2; e++) {
                int n = wn * 88 + t * 8 + lc + e;
                if (n < NTOK) pmax[half] = fmaxf(pmax[half], acc[t][half * 2 + e]);
            }
#pragma unroll
    for (int off = 1; off < 4; off <<= 1) {
        pmax[0] = fmaxf(pmax[0], __shfl_xor_sync(0xffffffffu, pmax[0], off, 4));
        pmax[1] = fmaxf(pmax[1], __shfl_xor_sync(0xffffffffu, pmax[1], off, 4));
    }
    if ((lane & 3) == 0) {
        redM[wn][wm * 16 + lr]     = pmax[0];
        redM[wn][wm * 16 + 8 + lr] = pmax[1];
    }
    __syncthreads();
    float mx[2] = { fmaxf(redM[0][wm * 16 + lr],     redM[1][wm * 16 + lr]),
                    fmaxf(redM[0][wm * 16 + 8 + lr], redM[1][wm * 16 + 8 + lr]) };
    float psum[2] = { 0.f, 0.f };
#pragma unroll
    for (int half = 0; half < 2; half++)
#pragma unroll
        for (int t = 0; t < 11; t++)
#pragma unroll
            for (int e = 0; e < 2; e++) {
                int n = wn * 88 + t * 8 + lc + e;
                float ev = (n < NTOK) ? __expf(acc[t][half * 2 + e] - mx[half]) : 0.f;
                acc[t][half * 2 + e] = ev;
                psum[half] += ev;
            }
#pragma unroll
    for (int off = 1; off < 4; off <<= 1) {
        psum[0] += __shfl_xor_sync(0xffffffffu, psum[0], off, 4);
        psum[1] += __shfl_xor_sync(0xffffffffu, psum[1], off, 4);
    }
    if ((lane & 3) == 0) {
        redS[wn][wm * 16 + lr]     = psum[0];
        redS[wn][wm * 16 + 8 + lr] = psum[1];
    }
    __syncthreads();
    float inv[2] = { 1.f / (redS[0][wm * 16 + lr]     + redS[1][wm * 16 + lr]),
                     1.f / (redS[0][wm * 16 + 8 + lr] + redS[1][wm * 16 + 8 + lr]) };
#pragma unroll
    for (int half = 0; half < 2; half++)
#pragma unroll
        for (int t = 0; t < 11; t++)
#pragma unroll
            for (int e = 0; e < 2; e++)
                acc[t][half * 2 + e] *= inv[half];
    __syncthreads();

    // += h_w @ f8 (K2 = 512), += u_w @ pool (K2 = 256)
    run_gemm(s, acc, g_hwh + (size_t)m0 * 512, g_hwl + (size_t)m0 * 512, 512,
             g_f8hl + (size_t)b * 512 * BNP, 512, tid, lane, wm, wn);
    run_gemm(s, acc, g_uwh + (size_t)m0 * 256, g_uwl + (size_t)m0 * 256, 256,
             g_phl + (size_t)b * 256 * BNP, 256, tid, lane, wm, wn);

    // ---- write S fp32 (stride 176; pad rows/cols remain 0) ----
#pragma unroll
    for (int half = 0; half < 2; half++) {
        int row = m0 + wm * 16 + lr + half * 8;
        if (row >= NTOK) continue;
        float bv = h_b[row] + u_b[row];
        float* srow = g_S + (size_t)b * 176 * 176 + (size_t)row * 176;
#pragma unroll
        for (int t = 0; t < 11; t++)
#pragma unroll
            for (int e = 0; e < 2; e++) {
                int n = wn * 88 + t * 8 + lc + e;
                if (n < NTOK) srow[n] = acc[t][half * 2 + e] + bv;
            }
    }
}

// ============================================================
// out = gamma * (c_w @ S + c_b) + x     grid (8, BATCH), K2 = 352
// ============================================================
__global__ __launch_bounds__(256, 2) void out_kernel(const float* __restrict__ c_b,
                                                     const float* __restrict__ x,
                                                     const float* __restrict__ gamma_p,
                                                     float* __restrict__ Out)
{
    __shared__ Smem s;
    int b   = blockIdx.y;
    int m0  = blockIdx.x * 64;
    int tid = threadIdx.x, lane = tid & 31, wid = tid >> 5;
    int wm = wid & 3, wn = wid >> 2;
    int lr = lane >> 2, lc = (lane & 3) * 2;

    float acc[11][4] = {};
    run_gemm(s, acc, g_cwh + (size_t)m0 * 352, g_cwl + (size_t)m0 * 352, 352,
             g_Shl + (size_t)b * 352 * BNP, 352, tid, lane, wm, wn);

    float gma = *gamma_p;
#pragma unroll
    for (int half = 0; half < 2; half++) {
        int m = m0 + wm * 16 + lr + half * 8;
        float bv = c_b[m];
        const float* xrow = x + (size_t)b * 512 * NTOK + (size_t)m * NTOK;
        float* orow = Out + (size_t)b * 512 * NTOK + (size_t)m * NTOK;
#pragma unroll
        for (int t = 0; t < 11; t++)
#pragma unroll
            for (int e = 0; e < 2; e++) {
                int n = wn * 88 + t * 8 + lc + e;
                if (n < NTOK)
                    orow[n] = fmaf(gma, acc[t][half * 2 + e] + bv, xrow[n]);
            }
    }
}

// ============================================================
extern "C" void kernel_launch(void* const* d_in, const int* in_sizes, int n_in,
                              void* d_out, int out_size)
{
    const float* x    = (const float*)d_in[0];
    const float* f5   = (const float*)d_in[1];
    const float* f8   = (const float*)d_in[2];
    const float* f_w  = (const float*)d_in[3];
    const float* f_b  = (const float*)d_in[4];
    const float* g_w  = (const float*)d_in[5];
    const float* g_b  = (const float*)d_in[6];
    const float* h_w  = (const float*)d_in[7];
    const float* h_b  = (const float*)d_in[8];
    const float* u_w  = (const float*)d_in[9];
    const float* u_b  = (const float*)d_in[10];
    const float* c_w  = (const float*)d_in[11];
    const float* c_b  = (const float*)d_in[12];
    const float* gma  = (const float*)d_in[13];

    float* out = (float*)d_out;

    int wtot = 2 * 64 * 512 + 169 * 256 + 169 * 128 + 512 * 169;
    split_w_kernel<<<(wtot + 255) / 256, 256>>>(f_w, g_w, h_w, u_w, c_w);
    split_x_kernel<<<(XE + FE + 255) / 256, 256>>>(x, f8);
    {
        int total = BATCH * 128 * NTOK;
        pool_kernel<<<(total + 255) / 256, 256>>>(f5);
    }
    fg_kernel<<<dim3(2, BATCH), 256>>>(f_b, g_b);
    s_kernel<<<dim3(3, BATCH), 256>>>(h_b, u_b);
    split_s_kernel<<<(BATCH * 176 * 176 + 255) / 256, 256>>>();
    out_kernel<<<dim3(8, BATCH), 256>>>(c_b, x, gma, out);
}

// round 8
// speedup vs baseline: 1.4054x; 1.0585x over previous
#include <cuda_runtime.h>
#include <cuda_bf16.h>
#include <math_constants.h>

#define HW 13
#define NTOK 169
#define BNP 192          // bf16 B-operand column stride
#define BATCH 256

typedef __nv_bfloat16 bf;

// ---- B-operand planes: [k][BNP] bf16, separate hi / lo ----
__device__ __align__(16) bf g_xh [BATCH * 512 * BNP], g_xl [BATCH * 512 * BNP];
__device__ __align__(16) bf g_f8h[BATCH * 256 * BNP], g_f8l[BATCH * 256 * BNP];
__device__ __align__(16) bf g_ph [BATCH * 128 * BNP], g_pl [BATCH * 128 * BNP];
__device__ __align__(16) bf g_Gh [BATCH * 64 * BNP],  g_Gl [BATCH * 64 * BNP];
__device__ __align__(16) bf g_Sh [BATCH * 176 * BNP], g_Sl [BATCH * 176 * BNP];
// ---- A-operand planes: [m][K] bf16 (row-major, K-contiguous) ----
__device__ __align__(16) bf g_fwh[64 * 512],  g_fwl[64 * 512];
__device__ __align__(16) bf g_gwh[64 * 512],  g_gwl[64 * 512];
__device__ __align__(16) bf g_hwh[192 * 256], g_hwl[192 * 256];
__device__ __align__(16) bf g_uwh[192 * 128], g_uwl[192 * 128];
__device__ __align__(16) bf g_cwh[512 * 176], g_cwl[512 * 176];
__device__ __align__(16) bf g_Fh [BATCH * 192 * 64], g_Fl[BATCH * 192 * 64];

// ============================================================
// low-level helpers
// ============================================================
__device__ __forceinline__ unsigned smem_u32(const void* p) {
    return (unsigned)__cvta_generic_to_shared(p);
}
__device__ __forceinline__ void cpa16(void* dst, const void* src) {
    asm volatile("cp.async.cg.shared.global [%0], [%1], 16;"
                 :: "r"(smem_u32(dst)), "l"(src));
}
#define CP_COMMIT()  asm volatile("cp.async.commit_group;")
#define CP_WAIT0()   asm volatile("cp.async.wait_group 0;")

__device__ __forceinline__ void ldsm_x4(unsigned (&r)[4], unsigned a) {
    asm volatile("ldmatrix.sync.aligned.m8n8.x4.shared.b16 {%0,%1,%2,%3}, [%4];"
        : "=r"(r[0]), "=r"(r[1]), "=r"(r[2]), "=r"(r[3]) : "r"(a));
}
__device__ __forceinline__ void ldsm_x4t(unsigned (&r)[4], unsigned a) {
    asm volatile("ldmatrix.sync.aligned.m8n8.x4.trans.shared.b16 {%0,%1,%2,%3}, [%4];"
        : "=r"(r[0]), "=r"(r[1]), "=r"(r[2]), "=r"(r[3]) : "r"(a));
}
__device__ __forceinline__ void ldsm_x2t(unsigned (&r)[2], unsigned a) {
    asm volatile("ldmatrix.sync.aligned.m8n8.x2.trans.shared.b16 {%0,%1}, [%2];"
        : "=r"(r[0]), "=r"(r[1]) : "r"(a));
}
__device__ __forceinline__ void mma16816(float (&d)[4], const unsigned (&a)[4],
                                         unsigned b0, unsigned b1) {
    asm volatile("mma.sync.aligned.m16n8k16.row.col.f32.bf16.bf16.f32 "
        "{%0,%1,%2,%3}, {%4,%5,%6,%7}, {%8,%9}, {%0,%1,%2,%3};"
        : "+f"(d[0]), "+f"(d[1]), "+f"(d[2]), "+f"(d[3])
        : "r"(a[0]), "r"(a[1]), "r"(a[2]), "r"(a[3]), "r"(b0), "r"(b1));
}
__device__ __forceinline__ void split_bf(float v, bf& hi, bf& lo) {
    hi = __float2bfloat16(v);
    lo = __float2bfloat16(v - __bfloat162float(hi));
}

// ============================================================
// smem: double-buffered, logical-K chunk = 16
// A: [64][24] bf16 per plane (pad 24 -> conflict-free ldmatrix)
// B: [16][184] bf16 per plane (pad 184 -> conflict-free ldmatrix.trans)
// total static: 2*(2*3072 + 2*5888) = 35840 B
// ============================================================
struct Smem {
    bf Ah[2][64][24];
    bf Al[2][64][24];
    bf Bh[2][16][184];
    bf Bl[2][16][184];
};

__device__ __forceinline__ void fill(Smem& s, int buf,
                                     const bf* __restrict__ Ah, const bf* __restrict__ Al,
                                     int lda,
                                     const bf* __restrict__ Bh, const bf* __restrict__ Bl,
                                     int k0, int tid)
{
    {   // A planes: 128 x 16B ops each
        int var = tid >> 7;             // 0 = hi, 1 = lo
        int j = tid & 127;
        int r = j >> 1, q = j & 1;
        const bf* src = (var ? Al : Ah) + (size_t)r * lda + k0 + q * 8;
        bf* dst = var ? &s.Al[buf][r][q * 8] : &s.Ah[buf][r][q * 8];
        cpa16(dst, src);
    }
#pragma unroll
    for (int i = 0; i < 3; i++) {       // B planes: 368 x 16B ops each (736 total)
        int idx = tid + i * 256;
        if (idx < 736) {
            int var = idx >= 368;
            int j = idx - (var ? 368 : 0);
            int rr = j / 23, q = j - rr * 23;
            const bf* src = (var ? Bl : Bh) + (size_t)(k0 + rr) * BNP + q * 8;
            bf* dst = var ? &s.Bl[buf][rr][q * 8] : &s.Bh[buf][rr][q * 8];
            cpa16(dst, src);
        }
    }
}

__device__ __forceinline__ void mma_chunk(float (&acc)[11][4], Smem& s, int buf,
                                          int lane, int wm, int wn)
{
    unsigned rsel = lane & 15;
    unsigned csel = (lane >> 4) << 3;   // 0 or 8
    unsigned ah[4], al[4];
    ldsm_x4(ah, smem_u32(&s.Ah[buf][wm * 16 + rsel][csel]));
    ldsm_x4(al, smem_u32(&s.Al[buf][wm * 16 + rsel][csel]));
#pragma unroll
    for (int g = 0; g < 5; g++) {
        unsigned bh[4], bl[4];
        ldsm_x4t(bh, smem_u32(&s.Bh[buf][rsel][wn * 88 + g * 16 + csel]));
        ldsm_x4t(bl, smem_u32(&s.Bl[buf][rsel][wn * 88 + g * 16 + csel]));
        mma16816(acc[2 * g],     ah, bh[0], bh[1]);
        mma16816(acc[2 * g],     ah, bl[0], bl[1]);
        mma16816(acc[2 * g],     al, bh[0], bh[1]);
        mma16816(acc[2 * g + 1], ah, bh[2], bh[3]);
        mma16816(acc[2 * g + 1], ah, bl[2], bl[3]);
        mma16816(acc[2 * g + 1], al, bh[2], bh[3]);
    }
    unsigned bh2[2], bl2[2];
    ldsm_x2t(bh2, smem_u32(&s.Bh[buf][rsel][wn * 88 + 80]));
    ldsm_x2t(bl2, smem_u32(&s.Bl[buf][rsel][wn * 88 + 80]));
    mma16816(acc[10], ah, bh2[0], bh2[1]);
    mma16816(acc[10], ah, bl2[0], bl2[1]);
    mma16816(acc[10], al, bh2[0], bh2[1]);
}

__device__ __forceinline__ void run_gemm(Smem& s, float (&acc)[11][4],
                                         const bf* __restrict__ Ah, const bf* __restrict__ Al,
                                         int lda,
                                         const bf* __restrict__ Bh, const bf* __restrict__ Bl,
                                         int K, int tid, int lane, int wm, int wn)
{
    int nt = K >> 4;
    fill(s, 0, Ah, Al, lda, Bh, Bl, 0, tid);
    CP_COMMIT();
    for (int t = 0; t < nt; t++) {
        CP_WAIT0();
        __syncthreads();
        if (t + 1 < nt) {
            fill(s, (t + 1) & 1, Ah, Al, lda, Bh, Bl, (t + 1) * 16, tid);
            CP_COMMIT();
        }
        mma_chunk(acc, s, t & 1, lane, wm, wn);
    }
    __syncthreads();
}

// ============================================================
// split / repack kernels
// ============================================================
__global__ __launch_bounds__(256) void split_w_kernel(
    const float* __restrict__ f_w, const float* __restrict__ g_w,
    const float* __restrict__ h_w, const float* __restrict__ u_w,
    const float* __restrict__ c_w)
{
    int idx = blockIdx.x * 256 + threadIdx.x;
    float v; bf *dh, *dl;
    if (idx < 64 * 512) {
        v = f_w[idx]; dh = g_fwh + idx; dl = g_fwl + idx;
    } else if ((idx -= 64 * 512) < 64 * 512) {
        v = g_w[idx]; dh = g_gwh + idx; dl = g_gwl + idx;
    } else if ((idx -= 64 * 512) < 169 * 256) {
        v = h_w[idx]; dh = g_hwh + idx; dl = g_hwl + idx;
    } else if ((idx -= 169 * 256) < 169 * 128) {
        v = u_w[idx]; dh = g_uwh + idx; dl = g_uwl + idx;
    } else if ((idx -= 169 * 128) < 512 * 169) {
        int m = idx / 169, k = idx - m * 169;
        v = c_w[idx];
        dh = g_cwh + (size_t)m * 176 + k; dl = g_cwl + (size_t)m * 176 + k;
    } else return;
    bf hi, lo; split_bf(v, hi, lo);
    *dh = hi; *dl = lo;
}

#define XE (BATCH * 512 * NTOK)
#define FE (BATCH * 256 * NTOK)
__global__ __launch_bounds__(256) void split_x_kernel(const float* __restrict__ x,
                                                      const float* __restrict__ f8)
{
    int idx = blockIdx.x * 256 + threadIdx.x;
    const float* src; bf *bh, *bl;
    if (idx < XE)              { src = x;  bh = g_xh;  bl = g_xl; }
    else if ((idx -= XE) < FE) { src = f8; bh = g_f8h; bl = g_f8l; }
    else return;
    int row = idx / NTOK, n = idx - row * NTOK;
    bf hi, lo; split_bf(src[idx], hi, lo);
    size_t o = (size_t)row * BNP + n;
    bh[o] = hi; bl[o] = lo;
}

// ============================================================
// antialiased bilinear 26 -> 13 (jax antialias=True), writes split bf16
// ============================================================
__constant__ int   c_tap0[HW] = { 0, 1, 3, 5, 7, 9,11,13,15,17,19,21,23};
__constant__ float c_wt[HW][4] = {
    {3.f/7.f, 3.f/7.f, 1.f/7.f, 0.f},
    {0.125f, 0.375f, 0.375f, 0.125f}, {0.125f, 0.375f, 0.375f, 0.125f},
    {0.125f, 0.375f, 0.375f, 0.125f}, {0.125f, 0.375f, 0.375f, 0.125f},
    {0.125f, 0.375f, 0.375f, 0.125f}, {0.125f, 0.375f, 0.375f, 0.125f},
    {0.125f, 0.375f, 0.375f, 0.125f}, {0.125f, 0.375f, 0.375f, 0.125f},
    {0.125f, 0.375f, 0.375f, 0.125f}, {0.125f, 0.375f, 0.375f, 0.125f},
    {0.125f, 0.375f, 0.375f, 0.125f},
    {1.f/7.f, 3.f/7.f, 3.f/7.f, 0.f}
};

__global__ __launch_bounds__(256) void pool_kernel(const float* __restrict__ f5) {
    int idx = blockIdx.x * blockDim.x + threadIdx.x;
    if (idx >= BATCH * 128 * NTOK) return;
    int n  = idx % NTOK;
    int bc = idx / NTOK;
    int j = n % HW, i = n / HW;
    const float* src = f5 + (size_t)bc * 26 * 26;
    int r0 = c_tap0[i], cc0 = c_tap0[j];
    float acc = 0.f;
#pragma unroll
    for (int ri = 0; ri < 4; ri++) {
        float wr = c_wt[i][ri];
        if (wr == 0.f) continue;
        int r = r0 + ri;
        float rowv = 0.f;
#pragma unroll
        for (int ci = 0; ci < 4; ci++) {
            float wc = c_wt[j][ci];
            if (wc == 0.f) continue;
            rowv = fmaf(wc, src[r * 26 + cc0 + ci], rowv);
        }
        acc = fmaf(wr, rowv, acc);
    }
    bf hi, lo; split_bf(acc, hi, lo);
    size_t o = (size_t)bc * BNP + n;
    g_ph[o] = hi; g_pl[o] = lo;
}

// ============================================================
// F / G projections: grid (2, BATCH)
// ============================================================
__global__ __launch_bounds__(256, 2) void fg_kernel(const float* __restrict__ f_b,
                                                    const float* __restrict__ g_b)
{
    __shared__ Smem s;
    int b   = blockIdx.y;
    bool isG = blockIdx.x != 0;
    int tid = threadIdx.x, lane = tid & 31, wid = tid >> 5;
    int wm = wid & 3, wn = wid >> 2;

    float acc[11][4] = {};
    run_gemm(s, acc, isG ? g_gwh : g_fwh, isG ? g_gwl : g_fwl, 512,
             g_xh + (size_t)b * 512 * BNP, g_xl + (size_t)b * 512 * BNP, 512,
             tid, lane, wm, wn);

    const float* bias = isG ? g_b : f_b;
    int lr = lane >> 2, lc = (lane & 3) * 2;
#pragma unroll
    for (int half = 0; half < 2; half++) {
        int m = wm * 16 + lr + half * 8;      // output channel 0..63
        float bv = bias[m];
#pragma unroll
        for (int t = 0; t < 11; t++) {
#pragma unroll
            for (int e = 0; e < 2; e++) {
                int n = wn * 88 + t * 8 + lc + e;
                if (n >= NTOK) continue;
                float v = acc[t][half * 2 + e] + bv;
                bf hi, lo; split_bf(v, hi, lo);
                if (isG) {
                    size_t o = (size_t)(b * 64 + m) * BNP + n;
                    g_Gh[o] = hi; g_Gl[o] = lo;
                } else {
                    size_t o = (size_t)(b * 192 + n) * 64 + m;
                    g_Fh[o] = hi; g_Fl[o] = lo;
                }
            }
        }
    }
}

// ============================================================
// S = softmax(F^T G) + h_w@f8 + u_w@pool + bias     grid (3, BATCH)
// writes split bf16 S planes directly
// ============================================================
__global__ __launch_bounds__(256, 2) void s_kernel(const float* __restrict__ h_b,
                                                   const float* __restrict__ u_b)
{
    __shared__ Smem s;
    __shared__ float redM[2][64], redS[2][64];
    int b   = blockIdx.y;
    int m0  = blockIdx.x * 64;
    int tid = threadIdx.x, lane = tid & 31, wid = tid >> 5;
    int wm = wid & 3, wn = wid >> 2;
    int lr = lane >> 2, lc = (lane & 3) * 2;

    float acc[11][4] = {};

    // energy = F^T G  (K = 64)
    run_gemm(s, acc, g_Fh + (size_t)(b * 192 + m0) * 64,
                     g_Fl + (size_t)(b * 192 + m0) * 64, 64,
             g_Gh + (size_t)b * 64 * BNP, g_Gl + (size_t)b * 64 * BNP, 64,
             tid, lane, wm, wn);

    // ---- softmax over cols (rows split across 2 N-warps) ----
    float pmax[2] = { -CUDART_INF_F, -CUDART_INF_F };
#pragma unroll
    for (int half = 0; half < 2; half++)
#pragma unroll
        for (int t = 0; t < 11; t++)
#pragma unroll
            for (int e = 0; e < 2; e++) {
                int n = wn * 88 + t * 8 + lc + e;
                if (n < NTOK) pmax[half] = fmaxf(pmax[half], acc[t][half * 2 + e]);
            }
#pragma unroll
    for (int off = 1; off < 4; off <<= 1) {
        pmax[0] = fmaxf(pmax[0], __shfl_xor_sync(0xffffffffu, pmax[0], off, 4));
        pmax[1] = fmaxf(pmax[1], __shfl_xor_sync(0xffffffffu, pmax[1], off, 4));
    }
    if ((lane & 3) == 0) {
        redM[wn][wm * 16 + lr]     = pmax[0];
        redM[wn][wm * 16 + 8 + lr] = pmax[1];
    }
    __syncthreads();
    float mx[2] = { fmaxf(redM[0][wm * 16 + lr],     redM[1][wm * 16 + lr]),
                    fmaxf(redM[0][wm * 16 + 8 + lr], redM[1][wm * 16 + 8 + lr]) };
    float psum[2] = { 0.f, 0.f };
#pragma unroll
    for (int half = 0; half < 2; half++)
#pragma unroll
        for (int t = 0; t < 11; t++)
#pragma unroll
            for (int e = 0; e < 2; e++) {
                int n = wn * 88 + t * 8 + lc + e;
                float ev = (n < NTOK) ? __expf(acc[t][half * 2 + e] - mx[half]) : 0.f;
                acc[t][half * 2 + e] = ev;
                psum[half] += ev;
            }
#pragma unroll
    for (int off = 1; off < 4; off <<= 1) {
        psum[0] += __shfl_xor_sync(0xffffffffu, psum[0], off, 4);
        psum[1] += __shfl_xor_sync(0xffffffffu, psum[1], off, 4);
    }
    if ((lane & 3) == 0) {
        redS[wn][wm * 16 + lr]     = psum[0];
        redS[wn][wm * 16 + 8 + lr] = psum[1];
    }
    __syncthreads();
    float inv[2] = { 1.f / (redS[0][wm * 16 + lr]     + redS[1][wm * 16 + lr]),
                     1.f / (redS[0][wm * 16 + 8 + lr] + redS[1][wm * 16 + 8 + lr]) };
#pragma unroll
    for (int half = 0; half < 2; half++)
#pragma unroll
        for (int t = 0; t < 11; t++)
#pragma unroll
            for (int e = 0; e < 2; e++)
                acc[t][half * 2 + e] *= inv[half];
    __syncthreads();

    // += h_w @ f8 (K=256), += u_w @ pool (K=128)
    run_gemm(s, acc, g_hwh + (size_t)m0 * 256, g_hwl + (size_t)m0 * 256, 256,
             g_f8h + (size_t)b * 256 * BNP, g_f8l + (size_t)b * 256 * BNP, 256,
             tid, lane, wm, wn);
    run_gemm(s, acc, g_uwh + (size_t)m0 * 128, g_uwl + (size_t)m0 * 128, 128,
             g_ph + (size_t)b * 128 * BNP, g_pl + (size_t)b * 128 * BNP, 128,
             tid, lane, wm, wn);

    // ---- write split S planes directly ----
#pragma unroll
    for (int half = 0; half < 2; half++) {
        int row = m0 + wm * 16 + lr + half * 8;
        if (row >= NTOK) continue;
        float bv = h_b[row] + u_b[row];
        size_t ro = (size_t)(b * 176 + row) * BNP;
#pragma unroll
        for (int t = 0; t < 11; t++)
#pragma unroll
            for (int e = 0; e < 2; e++) {
                int n = wn * 88 + t * 8 + lc + e;
                if (n < NTOK) {
                    bf hi, lo; split_bf(acc[t][half * 2 + e] + bv, hi, lo);
                    g_Sh[ro + n] = hi; g_Sl[ro + n] = lo;
                }
            }
    }
}

// ============================================================
// out = gamma * (c_w @ S + c_b) + x     grid (8, BATCH), K = 176
// ============================================================
__global__ __launch_bounds__(256, 2) void out_kernel(const float* __restrict__ c_b,
                                                     const float* __restrict__ x,
                                                     const float* __restrict__ gamma_p,
                                                     float* __restrict__ Out)
{
    __shared__ Smem s;
    int b   = blockIdx.y;
    int m0  = blockIdx.x * 64;
    int tid = threadIdx.x, lane = tid & 31, wid = tid >> 5;
    int wm = wid & 3, wn = wid >> 2;
    int lr = lane >> 2, lc = (lane & 3) * 2;

    float acc[11][4] = {};
    run_gemm(s, acc, g_cwh + (size_t)m0 * 176, g_cwl + (size_t)m0 * 176, 176,
             g_Sh + (size_t)b * 176 * BNP, g_Sl + (size_t)b * 176 * BNP, 176,
             tid, lane, wm, wn);

    float gma = *gamma_p;
#pragma unroll
    for (int half = 0; half < 2; half++) {
        int m = m0 + wm * 16 + lr + half * 8;
        float bv = c_b[m];
        const float* xrow = x + (size_t)b * 512 * NTOK + (size_t)m * NTOK;
        float* orow = Out + (size_t)b * 512 * NTOK + (size_t)m * NTOK;
#pragma unroll
        for (int t = 0; t < 11; t++)
#pragma unroll
            for (int e = 0; e < 2; e++) {
                int n = wn * 88 + t * 8 + lc + e;
                if (n < NTOK)
                    orow[n] = fmaf(gma, acc[t][half * 2 + e] + bv, xrow[n]);
            }
    }
}

// ============================================================
extern "C" void kernel_launch(void* const* d_in, const int* in_sizes, int n_in,
                              void* d_out, int out_size)
{
    const float* x    = (const float*)d_in[0];
    const float* f5   = (const float*)d_in[1];
    const float* f8   = (const float*)d_in[2];
    const float* f_w  = (const float*)d_in[3];
    const float* f_b  = (const float*)d_in[4];
    const float* g_w  = (const float*)d_in[5];
    const float* g_b  = (const float*)d_in[6];
    const float* h_w  = (const float*)d_in[7];
    const float* h_b  = (const float*)d_in[8];
    const float* u_w  = (const float*)d_in[9];
    const float* u_b  = (const float*)d_in[10];
    const float* c_w  = (const float*)d_in[11];
    const float* c_b  = (const float*)d_in[12];
    const float* gma  = (const float*)d_in[13];

    float* out = (float*)d_out;

    int wtot = 2 * 64 * 512 + 169 * 256 + 169 * 128 + 512 * 169;
    split_w_kernel<<<(wtot + 255) / 256, 256>>>(f_w, g_w, h_w, u_w, c_w);
    split_x_kernel<<<(XE + FE + 255) / 256, 256>>>(x, f8);
    {
        int total = BATCH * 128 * NTOK;
        pool_kernel<<<(total + 255) / 256, 256>>>(f5);
    }
    fg_kernel<<<dim3(2, BATCH), 256>>>(f_b, g_b);
    s_kernel<<<dim3(3, BATCH), 256>>>(h_b, u_b);
    out_kernel<<<dim3(8, BATCH), 256>>>(c_b, x, gma, out);
}

// round 9
// speedup vs baseline: 1.4355x; 1.0215x over previous
#include <cuda_runtime.h>
#include <cuda_bf16.h>
#include <math_constants.h>

#define HW 13
#define NTOK 169
#define BNP 192          // bf16 B-operand column stride
#define BATCH 256

typedef __nv_bfloat16 bf;

// ---- B-operand planes: [k][BNP] bf16, separate hi / lo ----
__device__ __align__(16) bf g_xh [BATCH * 512 * BNP], g_xl [BATCH * 512 * BNP];
__device__ __align__(16) bf g_f8h[BATCH * 256 * BNP], g_f8l[BATCH * 256 * BNP];
__device__ __align__(16) bf g_ph [BATCH * 128 * BNP], g_pl [BATCH * 128 * BNP];
__device__ __align__(16) bf g_Gh [BATCH * 64 * BNP],  g_Gl [BATCH * 64 * BNP];
__device__ __align__(16) bf g_Sh [BATCH * 192 * BNP], g_Sl [BATCH * 192 * BNP]; // rows 176+ stay 0
// ---- A-operand planes: [m][K] bf16 (row-major, K-contiguous) ----
__device__ __align__(16) bf g_fwh[64 * 512],  g_fwl[64 * 512];
__device__ __align__(16) bf g_gwh[64 * 512],  g_gwl[64 * 512];
__device__ __align__(16) bf g_hwh[192 * 256], g_hwl[192 * 256];
__device__ __align__(16) bf g_uwh[192 * 128], g_uwl[192 * 128];
__device__ __align__(16) bf g_cwh[512 * 192], g_cwl[512 * 192]; // cols 176+ stay 0
__device__ __align__(16) bf g_Fh [BATCH * 192 * 64], g_Fl[BATCH * 192 * 64];

// ============================================================
// low-level helpers
// ============================================================
__device__ __forceinline__ unsigned smem_u32(const void* p) {
    return (unsigned)__cvta_generic_to_shared(p);
}
__device__ __forceinline__ void cpa16(void* dst, const void* src) {
    asm volatile("cp.async.cg.shared.global [%0], [%1], 16;"
                 :: "r"(smem_u32(dst)), "l"(src));
}
#define CP_COMMIT()  asm volatile("cp.async.commit_group;")
#define CP_WAIT1()   asm volatile("cp.async.wait_group 1;")
#define CP_WAIT0()   asm volatile("cp.async.wait_group 0;")

__device__ __forceinline__ void ldsm_x4(unsigned (&r)[4], unsigned a) {
    asm volatile("ldmatrix.sync.aligned.m8n8.x4.shared.b16 {%0,%1,%2,%3}, [%4];"
        : "=r"(r[0]), "=r"(r[1]), "=r"(r[2]), "=r"(r[3]) : "r"(a));
}
__device__ __forceinline__ void ldsm_x4t(unsigned (&r)[4], unsigned a) {
    asm volatile("ldmatrix.sync.aligned.m8n8.x4.trans.shared.b16 {%0,%1,%2,%3}, [%4];"
        : "=r"(r[0]), "=r"(r[1]), "=r"(r[2]), "=r"(r[3]) : "r"(a));
}
__device__ __forceinline__ void ldsm_x2t(unsigned (&r)[2], unsigned a) {
    asm volatile("ldmatrix.sync.aligned.m8n8.x2.trans.shared.b16 {%0,%1}, [%2];"
        : "=r"(r[0]), "=r"(r[1]) : "r"(a));
}
__device__ __forceinline__ void mma16816(float (&d)[4], const unsigned (&a)[4],
                                         unsigned b0, unsigned b1) {
    asm volatile("mma.sync.aligned.m16n8k16.row.col.f32.bf16.bf16.f32 "
        "{%0,%1,%2,%3}, {%4,%5,%6,%7}, {%8,%9}, {%0,%1,%2,%3};"
        : "+f"(d[0]), "+f"(d[1]), "+f"(d[2]), "+f"(d[3])
        : "r"(a[0]), "r"(a[1]), "r"(a[2]), "r"(a[3]), "r"(b0), "r"(b1));
}
__device__ __forceinline__ void split_bf(float v, bf& hi, bf& lo) {
    hi = __float2bfloat16(v);
    lo = __float2bfloat16(v - __bfloat162float(hi));
}

// ============================================================
// dynamic smem: double-buffered, logical-K chunk = 32
// A: [64][40] bf16/plane (80B row stride -> conflict-free ldmatrix)
// B: [32][184] bf16/plane (368B row stride -> conflict-free ldmatrix.trans)
// total 67584 B
// ============================================================
struct Smem {
    bf Ah[2][64][40];
    bf Al[2][64][40];
    bf Bh[2][32][184];
    bf Bl[2][32][184];
};
#define SMEM_BYTES sizeof(Smem)

__device__ __forceinline__ void fill(Smem& s, int buf,
                                     const bf* __restrict__ Ah, const bf* __restrict__ Al,
                                     int lda,
                                     const bf* __restrict__ Bh, const bf* __restrict__ Bl,
                                     int k0, int tid)
{
#pragma unroll
    for (int i = 0; i < 2; i++) {       // A planes: 256 x 16B ops each (512 total)
        int idx = tid + i * 256;
        int var = idx >> 8;             // 0 = hi, 1 = lo
        int j = idx & 255;
        int r = j >> 2, q = j & 3;
        const bf* src = (var ? Al : Ah) + (size_t)r * lda + k0 + q * 8;
        bf* dst = var ? &s.Al[buf][r][q * 8] : &s.Ah[buf][r][q * 8];
        cpa16(dst, src);
    }
#pragma unroll
    for (int i = 0; i < 6; i++) {       // B planes: 704 x 16B ops each (1408 total)
        int idx = tid + i * 256;
        if (idx < 1408) {
            int var = idx >= 704;
            int j = idx - (var ? 704 : 0);
            int rr = j / 22, q = j - rr * 22;
            const bf* src = (var ? Bl : Bh) + (size_t)(k0 + rr) * BNP + q * 8;
            bf* dst = var ? &s.Bl[buf][rr][q * 8] : &s.Bh[buf][rr][q * 8];
            cpa16(dst, src);
        }
    }
}

__device__ __forceinline__ void mma_chunk(float (&acc)[11][4], Smem& s, int buf,
                                          int lane, int wm, int wn)
{
    unsigned rsel = lane & 15;
    unsigned csel = (lane >> 4) << 3;   // 0 or 8
#pragma unroll
    for (int ks = 0; ks < 32; ks += 16) {
        unsigned ah[4], al[4];
        ldsm_x4(ah, smem_u32(&s.Ah[buf][wm * 16 + rsel][ks + csel]));
        ldsm_x4(al, smem_u32(&s.Al[buf][wm * 16 + rsel][ks + csel]));
#pragma unroll
        for (int g = 0; g < 5; g++) {
            unsigned bh[4], bl[4];
            ldsm_x4t(bh, smem_u32(&s.Bh[buf][ks + rsel][wn * 88 + g * 16 + csel]));
            ldsm_x4t(bl, smem_u32(&s.Bl[buf][ks + rsel][wn * 88 + g * 16 + csel]));
            mma16816(acc[2 * g],     ah, bh[0], bh[1]);
            mma16816(acc[2 * g],     ah, bl[0], bl[1]);
            mma16816(acc[2 * g],     al, bh[0], bh[1]);
            mma16816(acc[2 * g + 1], ah, bh[2], bh[3]);
            mma16816(acc[2 * g + 1], ah, bl[2], bl[3]);
            mma16816(acc[2 * g + 1], al, bh[2], bh[3]);
        }
        unsigned bh2[2], bl2[2];
        ldsm_x2t(bh2, smem_u32(&s.Bh[buf][ks + rsel][wn * 88 + 80]));
        ldsm_x2t(bl2, smem_u32(&s.Bl[buf][ks + rsel][wn * 88 + 80]));
        mma16816(acc[10], ah, bh2[0], bh2[1]);
        mma16816(acc[10], ah, bl2[0], bl2[1]);
        mma16816(acc[10], al, bh2[0], bh2[1]);
    }
}

__device__ __forceinline__ void run_gemm(Smem& s, float (&acc)[11][4],
                                         const bf* __restrict__ Ah, const bf* __restrict__ Al,
                                         int lda,
                                         const bf* __restrict__ Bh, const bf* __restrict__ Bl,
                                         int K, int tid, int lane, int wm, int wn)
{
    int nt = K >> 5;
    fill(s, 0, Ah, Al, lda, Bh, Bl, 0, tid);
    CP_COMMIT();
    for (int t = 0; t < nt; t++) {
        if (t + 1 < nt) {
            fill(s, (t + 1) & 1, Ah, Al, lda, Bh, Bl, (t + 1) * 32, tid);
            CP_COMMIT();
            CP_WAIT1();
        } else {
            CP_WAIT0();
        }
        __syncthreads();
        mma_chunk(acc, s, t & 1, lane, wm, wn);
        __syncthreads();
    }
}

// ============================================================
// split / repack kernels
// ============================================================
__global__ __launch_bounds__(256) void split_w_kernel(
    const float* __restrict__ f_w, const float* __restrict__ g_w,
    const float* __restrict__ h_w, const float* __restrict__ u_w,
    const float* __restrict__ c_w)
{
    int idx = blockIdx.x * 256 + threadIdx.x;
    float v; bf *dh, *dl;
    if (idx < 64 * 512) {
        v = f_w[idx]; dh = g_fwh + idx; dl = g_fwl + idx;
    } else if ((idx -= 64 * 512) < 64 * 512) {
        v = g_w[idx]; dh = g_gwh + idx; dl = g_gwl + idx;
    } else if ((idx -= 64 * 512) < 169 * 256) {
        v = h_w[idx]; dh = g_hwh + idx; dl = g_hwl + idx;
    } else if ((idx -= 169 * 256) < 169 * 128) {
        v = u_w[idx]; dh = g_uwh + idx; dl = g_uwl + idx;
    } else if ((idx -= 169 * 128) < 512 * 169) {
        int m = idx / 169, k = idx - m * 169;
        v = c_w[idx];
        dh = g_cwh + (size_t)m * 192 + k; dl = g_cwl + (size_t)m * 192 + k;
    } else return;
    bf hi, lo; split_bf(v, hi, lo);
    *dh = hi; *dl = lo;
}

#define XE (BATCH * 512 * NTOK)
#define FE (BATCH * 256 * NTOK)
__global__ __launch_bounds__(256) void split_x_kernel(const float* __restrict__ x,
                                                      const float* __restrict__ f8)
{
    int idx = blockIdx.x * 256 + threadIdx.x;
    const float* src; bf *bh, *bl;
    if (idx < XE)              { src = x;  bh = g_xh;  bl = g_xl; }
    else if ((idx -= XE) < FE) { src = f8; bh = g_f8h; bl = g_f8l; }
    else return;
    int row = idx / NTOK, n = idx - row * NTOK;
    bf hi, lo; split_bf(src[idx], hi, lo);
    size_t o = (size_t)row * BNP + n;
    bh[o] = hi; bl[o] = lo;
}

// ============================================================
// antialiased bilinear 26 -> 13 (jax antialias=True), writes split bf16
// ============================================================
__constant__ int   c_tap0[HW] = { 0, 1, 3, 5, 7, 9,11,13,15,17,19,21,23};
__constant__ float c_wt[HW][4] = {
    {3.f/7.f, 3.f/7.f, 1.f/7.f, 0.f},
    {0.125f, 0.375f, 0.375f, 0.125f}, {0.125f, 0.375f, 0.375f, 0.125f},
    {0.125f, 0.375f, 0.375f, 0.125f}, {0.125f, 0.375f, 0.375f, 0.125f},
    {0.125f, 0.375f, 0.375f, 0.125f}, {0.125f, 0.375f, 0.375f, 0.125f},
    {0.125f, 0.375f, 0.375f, 0.125f}, {0.125f, 0.375f, 0.375f, 0.125f},
    {0.125f, 0.375f, 0.375f, 0.125f}, {0.125f, 0.375f, 0.375f, 0.125f},
    {0.125f, 0.375f, 0.375f, 0.125f},
    {1.f/7.f, 3.f/7.f, 3.f/7.f, 0.f}
};

__global__ __launch_bounds__(256) void pool_kernel(const float* __restrict__ f5) {
    int idx = blockIdx.x * blockDim.x + threadIdx.x;
    if (idx >= BATCH * 128 * NTOK) return;
    int n  = idx % NTOK;
    int bc = idx / NTOK;
    int j = n % HW, i = n / HW;
    const float* src = f5 + (size_t)bc * 26 * 26;
    int r0 = c_tap0[i], cc0 = c_tap0[j];
    float acc = 0.f;
#pragma unroll
    for (int ri = 0; ri < 4; ri++) {
        float wr = c_wt[i][ri];
        if (wr == 0.f) continue;
        int r = r0 + ri;
        float rowv = 0.f;
#pragma unroll
        for (int ci = 0; ci < 4; ci++) {
            float wc = c_wt[j][ci];
            if (wc == 0.f) continue;
            rowv = fmaf(wc, src[r * 26 + cc0 + ci], rowv);
        }
        acc = fmaf(wr, rowv, acc);
    }
    bf hi, lo; split_bf(acc, hi, lo);
    size_t o = (size_t)bc * BNP + n;
    g_ph[o] = hi; g_pl[o] = lo;
}

// ============================================================
// F / G projections: grid (2, BATCH)
// ============================================================
__global__ __launch_bounds__(256, 2) void fg_kernel(const float* __restrict__ f_b,
                                                    const float* __restrict__ g_b)
{
    extern __shared__ char smem_raw[];
    Smem& s = *reinterpret_cast<Smem*>(smem_raw);
    int b   = blockIdx.y;
    bool isG = blockIdx.x != 0;
    int tid = threadIdx.x, lane = tid & 31, wid = tid >> 5;
    int wm = wid & 3, wn = wid >> 2;

    float acc[11][4] = {};
    run_gemm(s, acc, isG ? g_gwh : g_fwh, isG ? g_gwl : g_fwl, 512,
             g_xh + (size_t)b * 512 * BNP, g_xl + (size_t)b * 512 * BNP, 512,
             tid, lane, wm, wn);

    const float* bias = isG ? g_b : f_b;
    int lr = lane >> 2, lc = (lane & 3) * 2;
#pragma unroll
    for (int half = 0; half < 2; half++) {
        int m = wm * 16 + lr + half * 8;      // output channel 0..63
        float bv = bias[m];
#pragma unroll
        for (int t = 0; t < 11; t++) {
#pragma unroll
            for (int e = 0; e < 2; e++) {
                int n = wn * 88 + t * 8 + lc + e;
                if (n >= NTOK) continue;
                float v = acc[t][half * 2 + e] + bv;
                bf hi, lo; split_bf(v, hi, lo);
                if (isG) {
                    size_t o = (size_t)(b * 64 + m) * BNP + n;
                    g_Gh[o] = hi; g_Gl[o] = lo;
                } else {
                    size_t o = (size_t)(b * 192 + n) * 64 + m;
                    g_Fh[o] = hi; g_Fl[o] = lo;
                }
            }
        }
    }
}

// ============================================================
// S = softmax(F^T G) + h_w@f8 + u_w@pool + bias     grid (3, BATCH)
// ============================================================
__global__ __launch_bounds__(256, 2) void s_kernel(const float* __restrict__ h_b,
                                                   const float* __restrict__ u_b)
{
    extern __shared__ char smem_raw[];
    Smem& s = *reinterpret_cast<Smem*>(smem_raw);
    __shared__ float redM[2][64], redS[2][64];
    int b   = blockIdx.y;
    int m0  = blockIdx.x * 64;
    int tid = threadIdx.x, lane = tid & 31, wid = tid >> 5;
    int wm = wid & 3, wn = wid >> 2;
    int lr = lane >> 2, lc = (lane & 3) * 2;

    float acc[11][4] = {};

    // energy = F^T G  (K = 64)
    run_gemm(s, acc, g_Fh + (size_t)(b * 192 + m0) * 64,
                     g_Fl + (size_t)(b * 192 + m0) * 64, 64,
             g_Gh + (size_t)b * 64 * BNP, g_Gl + (size_t)b * 64 * BNP, 64,
             tid, lane, wm, wn);

    // ---- softmax over cols (rows split across 2 N-warps) ----
    float pmax[2] = { -CUDART_INF_F, -CUDART_INF_F };
#pragma unroll
    for (int half = 0; half < 2; half++)
#pragma unroll
        for (int t = 0; t < 11; t++)
#pragma unroll
            for (int e = 0; e < 2; e++) {
                int n = wn * 88 + t * 8 + lc + e;
                if (n < NTOK) pmax[half] = fmaxf(pmax[half], acc[t][half * 2 + e]);
            }
#pragma unroll
    for (int off = 1; off < 4; off <<= 1) {
        pmax[0] = fmaxf(pmax[0], __shfl_xor_sync(0xffffffffu, pmax[0], off, 4));
        pmax[1] = fmaxf(pmax[1], __shfl_xor_sync(0xffffffffu, pmax[1], off, 4));
    }
    if ((lane & 3) == 0) {
        redM[wn][wm * 16 + lr]     = pmax[0];
        redM[wn][wm * 16 + 8 + lr] = pmax[1];
    }
    __syncthreads();
    float mx[2] = { fmaxf(redM[0][wm * 16 + lr],     redM[1][wm * 16 + lr]),
                    fmaxf(redM[0][wm * 16 + 8 + lr], redM[1][wm * 16 + 8 + lr]) };
    float psum[2] = { 0.f, 0.f };
#pragma unroll
    for (int half = 0; half < 2; half++)
#pragma unroll
        for (int t = 0; t < 11; t++)
#pragma unroll
            for (int e = 0; e < 2; e++) {
                int n = wn * 88 + t * 8 + lc + e;
                float ev = (n < NTOK) ? __expf(acc[t][half * 2 + e] - mx[half]) : 0.f;
                acc[t][half * 2 + e] = ev;
                psum[half] += ev;
            }
#pragma unroll
    for (int off = 1; off < 4; off <<= 1) {
        psum[0] += __shfl_xor_sync(0xffffffffu, psum[0], off, 4);
        psum[1] += __shfl_xor_sync(0xffffffffu, psum[1], off, 4);
    }
    if ((lane & 3) == 0) {
        redS[wn][wm * 16 + lr]     = psum[0];
        redS[wn][wm * 16 + 8 + lr] = psum[1];
    }
    __syncthreads();
    float inv[2] = { 1.f / (redS[0][wm * 16 + lr]     + redS[1][wm * 16 + lr]),
                     1.f / (redS[0][wm * 16 + 8 + lr] + redS[1][wm * 16 + 8 + lr]) };
#pragma unroll
    for (int half = 0; half < 2; half++)
#pragma unroll
        for (int t = 0; t < 11; t++)
#pragma unroll
            for (int e = 0; e < 2; e++)
                acc[t][half * 2 + e] *= inv[half];
    __syncthreads();

    // += h_w @ f8 (K=256), += u_w @ pool (K=128)
    run_gemm(s, acc, g_hwh + (size_t)m0 * 256, g_hwl + (size_t)m0 * 256, 256,
             g_f8h + (size_t)b * 256 * BNP, g_f8l + (size_t)b * 256 * BNP, 256,
             tid, lane, wm, wn);
    run_gemm(s, acc, g_uwh + (size_t)m0 * 128, g_uwl + (size_t)m0 * 128, 128,
             g_ph + (size_t)b * 128 * BNP, g_pl + (size_t)b * 128 * BNP, 128,
             tid, lane, wm, wn);

    // ---- write split S planes ----
#pragma unroll
    for (int half = 0; half < 2; half++) {
        int row = m0 + wm * 16 + lr + half * 8;
        if (row >= NTOK) continue;
        float bv = h_b[row] + u_b[row];
        size_t ro = (size_t)(b * 192 + row) * BNP;
#pragma unroll
        for (int t = 0; t < 11; t++)
#pragma unroll
            for (int e = 0; e < 2; e++) {
                int n = wn * 88 + t * 8 + lc + e;
                if (n < NTOK) {
                    bf hi, lo; split_bf(acc[t][half * 2 + e] + bv, hi, lo);
                    g_Sh[ro + n] = hi; g_Sl[ro + n] = lo;
                }
            }
    }
}

// ============================================================
// out = gamma * (c_w @ S + c_b) + x     grid (8, BATCH), K = 192 (padded)
// ============================================================
__global__ __launch_bounds__(256, 2) void out_kernel(const float* __restrict__ c_b,
                                                     const float* __restrict__ x,
                                                     const float* __restrict__ gamma_p,
                                                     float* __restrict__ Out)
{
    extern __shared__ char smem_raw[];
    Smem& s = *reinterpret_cast<Smem*>(smem_raw);
    int b   = blockIdx.y;
    int m0  = blockIdx.x * 64;
    int tid = threadIdx.x, lane = tid & 31, wid = tid >> 5;
    int wm = wid & 3, wn = wid >> 2;
    int lr = lane >> 2, lc = (lane & 3) * 2;

    float acc[11][4] = {};
    run_gemm(s, acc, g_cwh + (size_t)m0 * 192, g_cwl + (size_t)m0 * 192, 192,
             g_Sh + (size_t)b * 192 * BNP, g_Sl + (size_t)b * 192 * BNP, 192,
             tid, lane, wm, wn);

    float gma = *gamma_p;
#pragma unroll
    for (int half = 0; half < 2; half++) {
        int m = m0 + wm * 16 + lr + half * 8;
        float bv = c_b[m];
        const float* xrow = x + (size_t)b * 512 * NTOK + (size_t)m * NTOK;
        float* orow = Out + (size_t)b * 512 * NTOK + (size_t)m * NTOK;
#pragma unroll
        for (int t = 0; t < 11; t++)
#pragma unroll
            for (int e = 0; e < 2; e++) {
                int n = wn * 88 + t * 8 + lc + e;
                if (n < NTOK)
                    orow[n] = fmaf(gma, acc[t][half * 2 + e] + bv, xrow[n]);
            }
    }
}

// ============================================================
extern "C" void kernel_launch(void* const* d_in, const int* in_sizes, int n_in,
                              void* d_out, int out_size)
{
    const float* x    = (const float*)d_in[0];
    const float* f5   = (const float*)d_in[1];
    const float* f8   = (const float*)d_in[2];
    const float* f_w  = (const float*)d_in[3];
    const float* f_b  = (const float*)d_in[4];
    const float* g_w  = (const float*)d_in[5];
    const float* g_b  = (const float*)d_in[6];
    const float* h_w  = (const float*)d_in[7];
    const float* h_b  = (const float*)d_in[8];
    const float* u_w  = (const float*)d_in[9];
    const float* u_b  = (const float*)d_in[10];
    const float* c_w  = (const float*)d_in[11];
    const float* c_b  = (const float*)d_in[12];
    const float* gma  = (const float*)d_in[13];

    float* out = (float*)d_out;

    cudaFuncSetAttribute(fg_kernel,  cudaFuncAttributeMaxDynamicSharedMemorySize, (int)SMEM_BYTES);
    cudaFuncSetAttribute(s_kernel,   cudaFuncAttributeMaxDynamicSharedMemorySize, (int)SMEM_BYTES);
    cudaFuncSetAttribute(out_kernel, cudaFuncAttributeMaxDynamicSharedMemorySize, (int)SMEM_BYTES);

    int wtot = 2 * 64 * 512 + 169 * 256 + 169 * 128 + 512 * 169;
    split_w_kernel<<<(wtot + 255) / 256, 256>>>(f_w, g_w, h_w, u_w, c_w);
    split_x_kernel<<<(XE + FE + 255) / 256, 256>>>(x, f8);
    {
        int total = BATCH * 128 * NTOK;
        pool_kernel<<<(total + 255) / 256, 256>>>(f5);
    }
    fg_kernel<<<dim3(2, BATCH), 256, SMEM_BYTES>>>(f_b, g_b);
    s_kernel<<<dim3(3, BATCH), 256, SMEM_BYTES>>>(h_b, u_b);
    out_kernel<<<dim3(8, BATCH), 256, SMEM_BYTES>>>(c_b, x, gma, out);
}